// round 14
// baseline (speedup 1.0000x reference)
#include <cuda_runtime.h>
#include <cuda_bf16.h>
#include <cuda_fp16.h>
#include <stdint.h>
#include <math.h>

#define B_   2
#define L_   2048
#define H_   1024
#define NH_  4
#define R_   (B_ * L_)       // 4096 rows
#define NCH_ 64              // chunks of 32 per sequence
#define GIN_ 1056
#define MLPH_ 2048

// ---------------- scratch ----------------
__device__ __align__(128) float g_qkv[(size_t)R_ * 3 * H_];
__device__ __align__(128) float g_qp[R_ * H_];     // u (fp32)
__device__ __align__(128) float g_vp[R_ * H_];     // delta_out
__device__ __align__(128) float g_v[R_ * H_];      // conv+silu v
__device__ __align__(128) float g_beta[R_ * NH_];
__device__ __align__(128) float g_fs[R_ * H_];
__device__ __align__(128) float g_fl[R_ * H_];
__device__ __align__(128) float g_mlp[(size_t)R_ * MLPH_];
__device__ __align__(128) float g_logits[R_ * 16];

// fp16 tiles for the scan (emitted by precomp; A-side single precision)
__device__ __align__(128) __half g_tq[R_ * H_];
__device__ __align__(128) __half g_tw[R_ * H_];
__device__ __align__(128) __half g_tkt[(size_t)B_*NH_*NCH_*8192];   // kT [bh][n][256][32]
__device__ __align__(128) __half g_ta[(size_t)B_*NH_*NCH_*1024];    // attn [bh][n][32][32]

// fp16 weights [N][K] (QKV packed: 3072 x 1024)
__device__ __align__(128) __half g_wh[3 * H_ * H_];
__device__ __align__(128) __half g_w1h[MLPH_ * GIN_];
__device__ __align__(128) __half g_woh[H_ * H_];
// fp16 activations
__device__ __align__(128) __half g_xh[R_ * H_];   // x, later oc
__device__ __align__(128) __half g_gh[(size_t)R_ * GIN_];

// ---------------- asm helpers ----------------
__device__ __forceinline__ void cpa16(uint32_t dst, const void* src) {
    asm volatile("cp.async.cg.shared.global [%0], [%1], 16;" :: "r"(dst), "l"(src));
}
#define CPA_COMMIT asm volatile("cp.async.commit_group;")
#define SMEMU32(p) ((uint32_t)__cvta_generic_to_shared(p))

#define MMAH16816(d, a, b0, b1) \
  asm volatile("mma.sync.aligned.m16n8k16.row.col.f32.f16.f16.f32 " \
    "{%0,%1,%2,%3}, {%4,%5,%6,%7}, {%8,%9}, {%0,%1,%2,%3};" \
    : "+f"(d[0]), "+f"(d[1]), "+f"(d[2]), "+f"(d[3]) \
    : "r"(a[0]), "r"(a[1]), "r"(a[2]), "r"(a[3]), "r"(b0), "r"(b1))

#define LDSM4(r0, r1, r2, r3, addr) \
  asm volatile("ldmatrix.sync.aligned.m8n8.x4.shared.b16 {%0,%1,%2,%3}, [%4];" \
    : "=r"(r0), "=r"(r1), "=r"(r2), "=r"(r3) : "r"(addr))

// ---------------- elementwise fp32 -> fp16 cast ----------------
__global__ void split_kernel(const float* __restrict__ A,
                             __half* __restrict__ Ah, int n)
{
    int i = blockIdx.x * 256 + threadIdx.x;
    if (i < n) Ah[i] = __float2half(A[i]);
}

// ---------------- weight transpose to fp16 [N][K] ----------------
__global__ void wconv_kernel(const float* __restrict__ W,
                             __half* __restrict__ Th, int K, int N)
{
    __shared__ float t[32][33];
    int k0 = blockIdx.y * 32, n0 = blockIdx.x * 32;
    int tx = threadIdx.x, ty = threadIdx.y;
    for (int i = ty; i < 32; i += 8)
        t[i][tx] = W[(size_t)(k0 + i) * N + n0 + tx];
    __syncthreads();
    for (int i = ty; i < 32; i += 8)
        Th[(size_t)(n0 + i) * K + k0 + tx] = __float2half(t[tx][i]);
}

__global__ void wconv3_kernel(const float* __restrict__ Wq,
                              const float* __restrict__ Wk,
                              const float* __restrict__ Wv)
{
    __shared__ float t[32][33];
    int z = blockIdx.z;
    const float* W = (z == 0) ? Wq : (z == 1) ? Wk : Wv;
    int k0 = blockIdx.y * 32, n0 = blockIdx.x * 32;
    int tx = threadIdx.x, ty = threadIdx.y;
    for (int i = ty; i < 32; i += 8)
        t[i][tx] = W[(size_t)(k0 + i) * H_ + n0 + tx];
    __syncthreads();
    size_t base = (size_t)z * H_ * H_;
    for (int i = ty; i < 32; i += 8)
        g_wh[base + (size_t)(n0 + i) * H_ + k0 + tx] = __float2half(t[tx][i]);
}

// ---------------- fp16 tensor-core GEMM ----------------
#define ASTR 40
#define STAGE_HALVES (3 * 128 * ASTR)

__global__ __launch_bounds__(256) void gemm_bf(
    const __half* __restrict__ Ahg, const __half* __restrict__ Alg,
    const __half* __restrict__ Bg,
    const float* __restrict__ bias, float* __restrict__ C,
    int M, int N, int K, int act)
{
    extern __shared__ __half smh[];
    int tid = threadIdx.x;
    int row0 = blockIdx.y * 128, col0 = blockIdx.x * 128;
    int wid = tid >> 5, lane = tid & 31;
    int wm = (wid >> 1) * 32, wn = (wid & 1) * 64;
    int g = lane >> 2, t = lane & 3;
    int lr = lane & 7, seg = lane >> 3;
    bool two = (Alg != nullptr);

    float acc[2][8][4];
#pragma unroll
    for (int i = 0; i < 2; i++)
#pragma unroll
        for (int j = 0; j < 8; j++)
#pragma unroll
            for (int q = 0; q < 4; q++) acc[i][j][q] = 0.f;

    const __half* gsrc[3] = {Ahg, Alg, Bg};
    int gr0[3] = {row0, row0, col0};

    auto load_stage = [&](int s, int k0) {
        __half* sp = smh + s * STAGE_HALVES;
#pragma unroll
        for (int a = 0; a < 3; a++) {
            if (a == 1 && !two) continue;
#pragma unroll
            for (int q = 0; q < 2; q++) {
                int c = tid * 2 + q;
                int r = c >> 2, sg = c & 3;
                uint32_t d = SMEMU32(sp + a * 128 * ASTR + r * ASTR + sg * 8);
                cpa16(d, gsrc[a] + (size_t)(gr0[a] + r) * K + k0 + sg * 8);
            }
        }
        CPA_COMMIT;
    };

    load_stage(0, 0);
    int nk = K / 32;
    for (int ki = 0; ki < nk; ki++) {
        if (ki + 1 < nk) {
            load_stage((ki + 1) & 1, (ki + 1) * 32);
            asm volatile("cp.async.wait_group 1;");
        } else {
            asm volatile("cp.async.wait_group 0;");
        }
        __syncthreads();
        __half* sp = smh + (ki & 1) * STAGE_HALVES;
        __half* Ah = sp;
        __half* Al = sp + 128 * ASTR;
        __half* Bs = sp + 2 * 128 * ASTR;
#pragma unroll
        for (int ks = 0; ks < 2; ks++) {
            int ko = ks * 16;
            int arow = wm + lr + ((seg & 1) << 3);
            int acol = ko + ((seg >> 1) << 3);
            uint32_t afh[2][4], afl[2][4];
#pragma unroll
            for (int mi = 0; mi < 2; mi++) {
                LDSM4(afh[mi][0], afh[mi][1], afh[mi][2], afh[mi][3],
                      SMEMU32(&Ah[(arow + mi * 16) * ASTR + acol]));
                if (two)
                    LDSM4(afl[mi][0], afl[mi][1], afl[mi][2], afl[mi][3],
                          SMEMU32(&Al[(arow + mi * 16) * ASTR + acol]));
            }
            int brow = wn + lr + ((seg >> 1) << 3);
            int bcol = ko + ((seg & 1) << 3);
            uint32_t b4[4][4];
#pragma unroll
            for (int nip = 0; nip < 4; nip++)
                LDSM4(b4[nip][0], b4[nip][1], b4[nip][2], b4[nip][3],
                      SMEMU32(&Bs[(brow + nip * 16) * ASTR + bcol]));
#pragma unroll
            for (int ni = 0; ni < 8; ni++) {
                uint32_t b0 = b4[ni >> 1][(ni & 1) * 2];
                uint32_t b1 = b4[ni >> 1][(ni & 1) * 2 + 1];
                MMAH16816(acc[0][ni], afh[0], b0, b1);
                MMAH16816(acc[1][ni], afh[1], b0, b1);
            }
            if (two) {
#pragma unroll
                for (int ni = 0; ni < 8; ni++) {
                    uint32_t b0 = b4[ni >> 1][(ni & 1) * 2];
                    uint32_t b1 = b4[ni >> 1][(ni & 1) * 2 + 1];
                    MMAH16816(acc[0][ni], afl[0], b0, b1);
                    MMAH16816(acc[1][ni], afl[1], b0, b1);
                }
            }
        }
        __syncthreads();
    }

#pragma unroll
    for (int mi = 0; mi < 2; mi++)
#pragma unroll
        for (int ni = 0; ni < 8; ni++) {
            int r = row0 + wm + mi * 16 + g;
            int c = col0 + wn + ni * 8 + 2 * t;
            float v[4];
#pragma unroll
            for (int q = 0; q < 4; q++) {
                float x = acc[mi][ni][q];
                if (bias) x += bias[c + (q & 1)];
                if (act == 1) x = 0.5f * x * (1.f + erff(x * 0.70710678118654752f));
                v[q] = x;
            }
            *(float2*)(C + (size_t)r * N + c)       = make_float2(v[0], v[1]);
            *(float2*)(C + (size_t)(r + 8) * N + c) = make_float2(v[2], v[3]);
        }
}

// ---------------- beta (float4 vectorized) ----------------
__global__ void beta_kernel(const float* __restrict__ x, const float* __restrict__ Wb)
{
    int r = blockIdx.x * 4 + (threadIdx.x >> 5);
    int lane = threadIdx.x & 31;
    float acc0 = 0, acc1 = 0, acc2 = 0, acc3 = 0;
    const float* xr = x + (size_t)r * H_;
    for (int kk = lane * 4; kk < H_; kk += 128) {
        float4 xv = *(const float4*)(xr + kk);
#pragma unroll
        for (int e = 0; e < 4; e++) {
            float xs = (e == 0) ? xv.x : (e == 1) ? xv.y : (e == 2) ? xv.z : xv.w;
            float4 w = *(const float4*)(Wb + (kk + e) * 4);
            acc0 += xs * w.x; acc1 += xs * w.y; acc2 += xs * w.z; acc3 += xs * w.w;
        }
    }
#pragma unroll
    for (int off = 16; off; off >>= 1) {
        acc0 += __shfl_down_sync(~0u, acc0, off);
        acc1 += __shfl_down_sync(~0u, acc1, off);
        acc2 += __shfl_down_sync(~0u, acc2, off);
        acc3 += __shfl_down_sync(~0u, acc3, off);
    }
    if (lane == 0) {
        g_beta[r * 4 + 0] = 1.f / (1.f + expf(-acc0));
        g_beta[r * 4 + 1] = 1.f / (1.f + expf(-acc1));
        g_beta[r * 4 + 2] = 1.f / (1.f + expf(-acc2));
        g_beta[r * 4 + 3] = 1.f / (1.f + expf(-acc3));
    }
}

// ---------------- causal conv K=4 + silu for v only ----------------
__global__ void conv_v_kernel(const float* __restrict__ cv)
{
    int tid = blockIdx.x * blockDim.x + threadIdx.x;
    int c = tid & (H_ - 1);
    int r = tid >> 10;
    int b = r >> 11;
    int l = r & (L_ - 1);
    const float* wc = cv + c * 4;
    float acc = 0.f;
#pragma unroll
    for (int j = 0; j < 4; j++) {
        int ll = l - 3 + j;
        if (ll >= 0) acc += g_qkv[(size_t)(b * L_ + ll) * 3 * H_ + 2 * H_ + c] * wc[j];
    }
    g_v[tid] = acc / (1.f + expf(-acc));
}

// ---------------- delta precompute: fused q/k conv + silu, fp16 tile emit --------
#define RS 260
__global__ __launch_bounds__(256) void precomp_kernel(const float* __restrict__ cq,
                                                      const float* __restrict__ ck)
{
    extern __shared__ float sm[];
    float* Qs = sm;
    float* Ks = Qs + 32 * RS;
    float* KB = Ks + 32 * RS;
    float* VB = KB + 32 * RS;
    float* Am = VB + 32 * RS;
    float* Tm = Am + 1024;
    __shared__ float rbeta[32], qn_s[32], kn_s[32];

    int bhn = blockIdx.x;
    int n = bhn % NCH_; int bh = bhn / NCH_;
    int b = bh >> 2, h = bh & 3;
    int l0 = n * 32;
    int tid = threadIdx.x, wi = tid >> 5, lane = tid & 31;

    // fused conv+silu for q,k: thread = channel d (0..255), rolling window over rows
    {
        int d = tid;
        int gcol = h * 256 + d;
        float wq0 = cq[gcol * 4 + 0], wq1 = cq[gcol * 4 + 1],
              wq2 = cq[gcol * 4 + 2], wq3 = cq[gcol * 4 + 3];
        float wk0 = ck[gcol * 4 + 0], wk1 = ck[gcol * 4 + 1],
              wk2 = ck[gcol * 4 + 2], wk3 = ck[gcol * 4 + 3];
        float q3 = 0, q2 = 0, q1 = 0, k3 = 0, k2 = 0, k1 = 0;
#pragma unroll
        for (int j = 0; j < 3; j++) {           // rows l0-3 .. l0-1
            int ll = l0 - 3 + j;
            float qv = 0, kv = 0;
            if (ll >= 0) {
                const float* row = g_qkv + (size_t)(b * L_ + ll) * 3 * H_;
                qv = row[gcol];
                kv = row[H_ + gcol];
            }
            if (j == 0) { q3 = qv; k3 = kv; }
            else if (j == 1) { q2 = qv; k2 = kv; }
            else { q1 = qv; k1 = kv; }
        }
#pragma unroll 4
        for (int i = 0; i < 32; i++) {
            const float* row = g_qkv + (size_t)(b * L_ + l0 + i) * 3 * H_;
            float q0 = row[gcol];
            float k0 = row[H_ + gcol];
            float aq = q3 * wq0 + q2 * wq1 + q1 * wq2 + q0 * wq3;
            float ak = k3 * wk0 + k2 * wk1 + k1 * wk2 + k0 * wk3;
            Qs[i * RS + d] = aq / (1.f + expf(-aq));
            Ks[i * RS + d] = ak / (1.f + expf(-ak));
            q3 = q2; q2 = q1; q1 = q0;
            k3 = k2; k2 = k1; k1 = k0;
        }
    }
    if (tid < 32) rbeta[tid] = g_beta[(b * L_ + l0 + tid) * 4 + h];
    __syncthreads();

    for (int rr = wi; rr < 32; rr += 8) {
        float sq = 0, sk = 0;
        for (int d = lane; d < 256; d += 32) {
            float a = Qs[rr * RS + d]; sq += a * a;
            float c = Ks[rr * RS + d]; sk += c * c;
        }
#pragma unroll
        for (int off = 16; off; off >>= 1) {
            sq += __shfl_down_sync(~0u, sq, off);
            sk += __shfl_down_sync(~0u, sk, off);
        }
        if (lane == 0) { qn_s[rr] = rsqrtf(sq + 1e-6f); kn_s[rr] = rsqrtf(sk + 1e-6f); }
    }
    __syncthreads();

    for (int e = tid; e < 8192; e += 256) {
        int i = e >> 8, d = e & 255;
        size_t gi = ((size_t)(b * L_ + l0 + i) << 10) + h * 256 + d;
        float qv = Qs[i * RS + d] * qn_s[i]; Qs[i * RS + d] = qv;
        float kv = Ks[i * RS + d] * kn_s[i]; Ks[i * RS + d] = kv;
        KB[i * RS + d] = kv * rbeta[i];
        VB[i * RS + d] = g_v[gi] * rbeta[i];
        g_tq[gi] = __float2half(qv);
    }
    __syncthreads();

    {
        size_t ckb = ((size_t)bh * NCH_ + n) * 8192;
        for (int e4 = tid; e4 < 2048; e4 += 256) {
            int i = e4 & 31, d0 = (e4 >> 5) * 4;
            float4 kv = *(const float4*)(Ks + i * RS + d0);
            g_tkt[ckb + (size_t)(d0 + 0) * 32 + i] = __float2half(kv.x);
            g_tkt[ckb + (size_t)(d0 + 1) * 32 + i] = __float2half(kv.y);
            g_tkt[ckb + (size_t)(d0 + 2) * 32 + i] = __float2half(kv.z);
            g_tkt[ckb + (size_t)(d0 + 3) * 32 + i] = __float2half(kv.w);
        }
    }

    for (int e = tid; e < 1024; e += 256) {
        int i = e >> 5, j = e & 31;
        float s = 0.f;
        if (j < i) {
            const float4* a = (const float4*)(KB + i * RS);
            const float4* c = (const float4*)(Ks + j * RS);
#pragma unroll 8
            for (int d = 0; d < 64; d++) {
                float4 av = a[d], cv = c[d];
                s += av.x * cv.x + av.y * cv.y + av.z * cv.z + av.w * cv.w;
            }
        }
        Am[e] = s;
    }
    __syncthreads();

    if (wi == 0) {
        int j = lane;
        for (int i = 0; i < 32; i++) {
            float val = (i == j) ? 1.f : 0.f;
            for (int m = j; m < i; m++) val -= Am[i * 32 + m] * Tm[m * 32 + j];
            Tm[i * 32 + j] = val;
            __syncwarp();
        }
    }
    __syncthreads();

    {
        size_t ab = ((size_t)bh * NCH_ + n) * 1024;
        for (int e = tid; e < 1024; e += 256) {
            int i = e >> 5, j = e & 31;
            float s = 0.f;
            if (j <= i) {
                const float4* a = (const float4*)(Qs + i * RS);
                const float4* c = (const float4*)(Ks + j * RS);
#pragma unroll 8
                for (int d = 0; d < 64; d++) {
                    float4 av = a[d], cv = c[d];
                    s += av.x * cv.x + av.y * cv.y + av.z * cv.z + av.w * cv.w;
                }
            }
            g_ta[ab + e] = __float2half(s);
        }
    }

    for (int e4 = tid; e4 < 2048; e4 += 256) {
        int i = e4 >> 6, d0 = (e4 & 63) * 4;
        float4 su = make_float4(0.f, 0.f, 0.f, 0.f);
        float4 sw = make_float4(0.f, 0.f, 0.f, 0.f);
        const float* tr = Tm + i * 32;
#pragma unroll
        for (int m = 0; m < 32; m++) {
            float t = tr[m];
            float4 vb = *(const float4*)(VB + m * RS + d0);
            float4 kb = *(const float4*)(KB + m * RS + d0);
            su.x += t * vb.x; su.y += t * vb.y; su.z += t * vb.z; su.w += t * vb.w;
            sw.x += t * kb.x; sw.y += t * kb.y; sw.z += t * kb.z; sw.w += t * kb.w;
        }
        size_t gi = ((size_t)(b * L_ + l0 + i) << 10) + h * 256 + d0;
        *(float4*)(g_qp + gi) = su;
        __half2* wp = (__half2*)(g_tw + gi);
        wp[0] = __floats2half2_rn(sw.x, sw.y);
        wp[1] = __floats2half2_rn(sw.z, sw.w);
    }
}

// ---------------- tensor-core scan ----------------
#define SC_SMEM 135168
#define STG_OFF 58368
#define STG_SZ  38400

__global__ __launch_bounds__(256) void scan_kernel()
{
    extern __shared__ char sc[];
    float* S  = (float*)sc;
    float* U2 = (float*)(sc + 16384);
    __half* SbTh = (__half*)(sc + 18432);
    __half* SbTl = (__half*)(sc + 26880);
    __half* U2Th = (__half*)(sc + 35328);
    __half* U2Tl = (__half*)(sc + 36608);
    __half* KT   = (__half*)(sc + 37888);

    int blk = blockIdx.x;
    int bh = blk >> 4, slice = blk & 15;
    int b = bh >> 2, h = bh & 3;
    int tid = threadIdx.x;
    int wi = tid >> 5, lane = tid & 31;
    int g = lane >> 2, t4 = lane & 3;
    int dvb = h * 256 + slice * 16;

    for (int e = tid; e < 4096; e += 256) S[e] = 0.f;
    for (int e = tid; e < 16 * 264; e += 256) {
        SbTh[e] = __float2half(0.f);
        SbTl[e] = __float2half(0.f);
    }

    auto issue_main = [&](int n, int buf) {
        char* sp = sc + STG_OFF + buf * STG_SZ;
        __half* Wt = (__half*)sp;
        __half* Qt = (__half*)(sp + 16896);
        float*  Uf = (float*)(sp + 33792);
        __half* At = (__half*)(sp + 35840);
        int row0 = b * L_ + n * 32;
#pragma unroll
        for (int it = 0; it < 8; it++) {
            int c = tid + it * 256;
            int a = c >> 10, rem = c & 1023;
            int r = rem >> 5, s = rem & 31;
            __half* dst = a ? Qt : Wt;
            const __half* src = a ? g_tq : g_tw;
            cpa16(SMEMU32(dst + r * 264 + s * 8),
                  src + ((size_t)(row0 + r) << 10) + h * 256 + s * 8);
        }
        if (tid < 128) {
            int r = tid >> 2, s = tid & 3;
            cpa16(SMEMU32(Uf + r * 16 + s * 4),
                  g_qp + ((size_t)(row0 + r) << 10) + dvb + s * 4);
        }
        if (tid < 128) {
            int r = tid >> 2, s = tid & 3;
            cpa16(SMEMU32(At + r * 40 + s * 8),
                  g_ta + ((size_t)bh * NCH_ + n) * 1024 + r * 32 + s * 8);
        }
        CPA_COMMIT;
    };

    auto issue_kT = [&](int n) {
        size_t base = ((size_t)bh * NCH_ + n) * 8192;
#pragma unroll
        for (int it = 0; it < 4; it++) {
            int c = tid + it * 256;
            int r = c >> 2, s = c & 3;
            cpa16(SMEMU32(KT + r * 40 + s * 8), g_tkt + base + r * 32 + s * 8);
        }
        CPA_COMMIT;
    };

    issue_main(0, 0);
    issue_kT(0);
    int buf = 0;

#pragma unroll 1
    for (int n = 0; n < NCH_; n++) {
        asm volatile("cp.async.wait_group 0;");
        if (n + 1 < NCH_) issue_main(n + 1, buf ^ 1);
        __syncthreads();

        char* sp = sc + STG_OFF + buf * STG_SZ;
        const __half* Wt = (const __half*)sp;
        const __half* Qt = (const __half*)(sp + 16896);
        const float*  Uf = (const float*)(sp + 33792);
        const __half* At = (const __half*)(sp + 35840);

        float c0[4] = {0,0,0,0}, c1[4] = {0,0,0,0};
        int w4 = wi & 3;
        int m0 = (w4 >> 1) * 16, n0 = (w4 & 1) * 8;
        const __half* Am_ = (wi < 4) ? Wt : Qt;
#pragma unroll
        for (int kk = 0; kk < 16; kk++) {
            int ka = kk * 16 + 2 * t4;
            uint32_t ah[4];
            ah[0] = *(const uint32_t*)&Am_[(m0 + g) * 264 + ka];
            ah[1] = *(const uint32_t*)&Am_[(m0 + 8 + g) * 264 + ka];
            ah[2] = *(const uint32_t*)&Am_[(m0 + g) * 264 + ka + 8];
            ah[3] = *(const uint32_t*)&Am_[(m0 + 8 + g) * 264 + ka + 8];
            uint32_t bh0 = *(const uint32_t*)&SbTh[(n0 + g) * 264 + ka];
            uint32_t bh1 = *(const uint32_t*)&SbTh[(n0 + g) * 264 + ka + 8];
            uint32_t bl0 = *(const uint32_t*)&SbTl[(n0 + g) * 264 + ka];
            uint32_t bl1 = *(const uint32_t*)&SbTl[(n0 + g) * 264 + ka + 8];
            MMAH16816(c0, ah, bh0, bh1);
            MMAH16816(c1, ah, bl0, bl1);
        }
        if (wi < 4) {
            U2[(m0 + g) * 16 + n0 + 2 * t4]         = Uf[(m0 + g) * 16 + n0 + 2 * t4]         - (c0[0] + c1[0]);
            U2[(m0 + g) * 16 + n0 + 2 * t4 + 1]     = Uf[(m0 + g) * 16 + n0 + 2 * t4 + 1]     - (c0[1] + c1[1]);
            U2[(m0 + 8 + g) * 16 + n0 + 2 * t4]     = Uf[(m0 + 8 + g) * 16 + n0 + 2 * t4]     - (c0[2] + c1[2]);
            U2[(m0 + 8 + g) * 16 + n0 + 2 * t4 + 1] = Uf[(m0 + 8 + g) * 16 + n0 + 2 * t4 + 1] - (c0[3] + c1[3]);
        }
        __syncthreads();

#pragma unroll
        for (int q2 = 0; q2 < 2; q2++) {
            int e = tid + q2 * 256;
            int i2 = e >> 4, j2 = e & 15;
            float v = U2[i2 * 16 + j2];
            __half hv = __float2half(v);
            U2Th[j2 * 40 + i2] = hv;
            U2Tl[j2 * 40 + i2] = __float2half(v - __half2float(hv));
        }
        __syncthreads();

        if (wi >= 4) {
#pragma unroll
            for (int kk = 0; kk < 2; kk++) {
                int ka = kk * 16 + 2 * t4;
                uint32_t ah[4];
                ah[0] = *(const uint32_t*)&At[(m0 + g) * 40 + ka];
                ah[1] = *(const uint32_t*)&At[(m0 + 8 + g) * 40 + ka];
                ah[2] = *(const uint32_t*)&At[(m0 + g) * 40 + ka + 8];
                ah[3] = *(const uint32_t*)&At[(m0 + 8 + g) * 40 + ka + 8];
                uint32_t bh0 = *(const uint32_t*)&U2Th[(n0 + g) * 40 + ka];
                uint32_t bh1 = *(const uint32_t*)&U2Th[(n0 + g) * 40 + ka + 8];
                uint32_t bl0 = *(const uint32_t*)&U2Tl[(n0 + g) * 40 + ka];
                uint32_t bl1 = *(const uint32_t*)&U2Tl[(n0 + g) * 40 + ka + 8];
                MMAH16816(c0, ah, bh0, bh1);
                MMAH16816(c1, ah, bl0, bl1);
            }
            size_t ob = ((size_t)(b * L_ + n * 32) << 10) + dvb + n0 + 2 * t4;
            *(float2*)(g_vp + ob + ((size_t)(m0 + g) << 10)) =
                make_float2(c0[0] + c1[0], c0[1] + c1[1]);
            *(float2*)(g_vp + ob + ((size_t)(m0 + 8 + g) << 10)) =
                make_float2(c0[2] + c1[2], c0[3] + c1[3]);
        }

#pragma unroll
        for (int mm = 0; mm < 2; mm++)
#pragma unroll
        for (int nn = 0; nn < 2; nn++) {
            int m0p = (wi * 2 + mm) * 16, n0p = nn * 8;
            float d0[4];
            float2 s01 = *(float2*)(S + (m0p + g) * 16 + n0p + 2 * t4);
            float2 s23 = *(float2*)(S + (m0p + 8 + g) * 16 + n0p + 2 * t4);
            d0[0] = s01.x; d0[1] = s01.y; d0[2] = s23.x; d0[3] = s23.y;
#pragma unroll
            for (int kk = 0; kk < 2; kk++) {
                int ka = kk * 16 + 2 * t4;
                uint32_t ah[4];
                ah[0] = *(const uint32_t*)&KT[(m0p + g) * 40 + ka];
                ah[1] = *(const uint32_t*)&KT[(m0p + 8 + g) * 40 + ka];
                ah[2] = *(const uint32_t*)&KT[(m0p + g) * 40 + ka + 8];
                ah[3] = *(const uint32_t*)&KT[(m0p + 8 + g) * 40 + ka + 8];
                uint32_t bh0 = *(const uint32_t*)&U2Th[(n0p + g) * 40 + ka];
                uint32_t bh1 = *(const uint32_t*)&U2Th[(n0p + g) * 40 + ka + 8];
                uint32_t bl0 = *(const uint32_t*)&U2Tl[(n0p + g) * 40 + ka];
                uint32_t bl1 = *(const uint32_t*)&U2Tl[(n0p + g) * 40 + ka + 8];
                MMAH16816(d0, ah, bh0, bh1);
                MMAH16816(d0, ah, bl0, bl1);
            }
            *(float2*)(S + (m0p + g) * 16 + n0p + 2 * t4)     = make_float2(d0[0], d0[1]);
            *(float2*)(S + (m0p + 8 + g) * 16 + n0p + 2 * t4) = make_float2(d0[2], d0[3]);
        }
        __syncthreads();

        if (n + 1 < NCH_) issue_kT(n + 1);

        {
            int j = tid & 15, kb = tid >> 4;
#pragma unroll
            for (int m = 0; m < 16; m++) {
                int k = kb + m * 16;
                float v = S[k * 16 + j];
                __half hv = __float2half(v);
                SbTh[j * 264 + k] = hv;
                SbTl[j * 264 + k] = __float2half(v - __half2float(hv));
            }
        }
        __syncthreads();
        buf ^= 1;
    }
}

// ---------------- FIR convs ----------------
__global__ __launch_bounds__(256) void fir_kernel(const float* __restrict__ ws,
                                                  const float* __restrict__ wl)
{
    __shared__ float vt[94][64];
    __shared__ float wls[64 * 63];
    __shared__ float wss[64 * 3];
    int cb = blockIdx.x;
    int lb = blockIdx.y;
    int b = lb >> 6;
    int l0 = (lb & 63) * 32;
    int c0 = cb * 64;
    int tid = threadIdx.x;

    for (int e = tid; e < 94 * 64; e += 256) {
        int rr = e >> 6, cc = e & 63;
        int l = l0 - 62 + rr;
        vt[rr][cc] = (l >= 0) ? g_v[((size_t)(b * L_ + l) << 10) + c0 + cc] : 0.f;
    }
    for (int e = tid; e < 64 * 63; e += 256) wls[e] = wl[(size_t)c0 * 63 + e];
    for (int e = tid; e < 64 * 3; e += 256)  wss[e] = ws[(size_t)c0 * 3 + e];
    __syncthreads();

    for (int e = tid; e < 32 * 64; e += 256) {
        int i = e >> 6, cc = e & 63;
        float aL = 0.f, aS = 0.f;
        const float* wlr = wls + cc * 63;
#pragma unroll 9
        for (int j = 0; j < 63; j++) aL += vt[i + j][cc] * wlr[j];
        const float* wsr = wss + cc * 3;
#pragma unroll
        for (int j = 0; j < 3; j++) aS += vt[i + 60 + j][cc] * wsr[j];
        size_t gi = ((size_t)(b * L_ + l0 + i) << 10) + c0 + cc;
        g_fl[gi] = aL;
        g_fs[gi] = aS;
    }
}

// ---------------- gate input: write fp16 directly ----------------
__global__ void gate_kernel(const float* __restrict__ x)
{
    __shared__ float stats[32];
    int r = blockIdx.x, tid = threadIdx.x;
    int wi = tid >> 5, lane = tid & 31;
    for (int p = wi; p < 16; p += 8) {
        int br = p >> 2, h = p & 3;
        const float* src = (br == 0 ? g_fs : br == 1 ? g_fl : br == 2 ? g_vp : g_v)
                           + ((size_t)r << 10) + h * 256;
        float s = 0, s2 = 0;
        for (int d = lane; d < 256; d += 32) { float t = src[d]; s += t; s2 += t * t; }
#pragma unroll
        for (int off = 16; off; off >>= 1) {
            s += __shfl_down_sync(~0u, s, off);
            s2 += __shfl_down_sync(~0u, s2, off);
        }
        if (lane == 0) {
            float mean = s * (1.f / 256.f);
            float var = s2 * (1.f / 256.f) - mean * mean;
            stats[br * 8 + h] = mean;
            stats[br * 8 + 4 + h] = sqrtf(fmaxf(var, 1e-6f));
        }
    }
    __syncthreads();
    const float* xr = x + (size_t)r * H_;
    size_t gb = (size_t)r * GIN_;
    for (int e = tid; e < GIN_; e += 256) {
        float v = (e < H_) ? xr[e] : stats[e - H_];
        g_gh[gb + e] = __float2half(v);
    }
}

// ---------------- MLP2 ----------------
__global__ void mlp2_kernel(const float* __restrict__ w2, const float* __restrict__ b2)
{
    int r = blockIdx.x, tid = threadIdx.x;
    float acc[16];
#pragma unroll
    for (int o = 0; o < 16; o++) acc[o] = 0.f;
    const float* hr = g_mlp + (size_t)r * MLPH_;
    for (int kk = tid; kk < MLPH_; kk += 128) {
        float hv = hr[kk];
        const float4* wr = (const float4*)(w2 + (size_t)kk * 16);
        float4 w0 = wr[0], w1 = wr[1], w2v = wr[2], w3 = wr[3];
        acc[0] += hv * w0.x; acc[1] += hv * w0.y; acc[2] += hv * w0.z; acc[3] += hv * w0.w;
        acc[4] += hv * w1.x; acc[5] += hv * w1.y; acc[6] += hv * w1.z; acc[7] += hv * w1.w;
        acc[8] += hv * w2v.x; acc[9] += hv * w2v.y; acc[10] += hv * w2v.z; acc[11] += hv * w2v.w;
        acc[12] += hv * w3.x; acc[13] += hv * w3.y; acc[14] += hv * w3.z; acc[15] += hv * w3.w;
    }
    __shared__ float part[4][16];
    int wi = tid >> 5, lane = tid & 31;
#pragma unroll
    for (int o = 0; o < 16; o++) {
        float v = acc[o];
#pragma unroll
        for (int off = 16; off; off >>= 1) v += __shfl_down_sync(~0u, v, off);
        if (lane == 0) part[wi][o] = v;
    }
    __syncthreads();
    if (tid < 16)
        g_logits[r * 16 + tid] =
            part[0][tid] + part[1][tid] + part[2][tid] + part[3][tid] + b2[tid];
}

// ---------------- combine + RMSNorm ----------------
__global__ void combine_kernel(const float* __restrict__ ltemp,
                               const float* __restrict__ onw)
{
    int r = blockIdx.x, tid = threadIdx.x;
    int wi = tid >> 5, lane = tid & 31;
    __shared__ float wsum[8];
    __shared__ float bcast;
    const float* lg = g_logits + r * 16;
#pragma unroll 1
    for (int h = 0; h < 4; h++) {
        float temp = log1pf(expf(ltemp[h])) + 1e-4f;
        float l0 = lg[h * 4 + 0] / temp, l1 = lg[h * 4 + 1] / temp;
        float l2 = lg[h * 4 + 2] / temp, l3 = lg[h * 4 + 3] / temp;
        float mx = fmaxf(fmaxf(l0, l1), fmaxf(l2, l3));
        float e0 = expf(l0 - mx), e1 = expf(l1 - mx), e2 = expf(l2 - mx), e3 = expf(l3 - mx);
        float inv = 1.f / (e0 + e1 + e2 + e3);
        size_t idx = ((size_t)r << 10) + h * 256 + tid;
        float ov = (e0 * g_fs[idx] + e1 * g_fl[idx] + e2 * g_vp[idx] + e3 * g_v[idx]) * inv;
        float sq = ov * ov;
#pragma unroll
        for (int off = 16; off; off >>= 1) sq += __shfl_down_sync(~0u, sq, off);
        if (lane == 0) wsum[wi] = sq;
        __syncthreads();
        if (tid == 0) {
            float s = 0.f;
#pragma unroll
            for (int q = 0; q < 8; q++) s += wsum[q];
            bcast = rsqrtf(s * (1.f / 256.f) + 1e-5f);
        }
        __syncthreads();
        float val = ov * bcast * onw[tid];
        g_xh[idx] = __float2half(val);
        __syncthreads();
    }
}

// ---------------- launch ----------------
extern "C" void kernel_launch(void* const* d_in, const int* in_sizes, int n_in,
                              void* d_out, int out_size)
{
    const float* x   = (const float*)d_in[0];
    const float* Wq  = (const float*)d_in[1];
    const float* Wk  = (const float*)d_in[2];
    const float* Wv  = (const float*)d_in[3];
    const float* Wb  = (const float*)d_in[4];
    const float* cq  = (const float*)d_in[5];
    const float* ck  = (const float*)d_in[6];
    const float* cv  = (const float*)d_in[7];
    const float* fsw = (const float*)d_in[8];
    const float* flw = (const float*)d_in[9];
    const float* w1  = (const float*)d_in[10];
    const float* b1  = (const float*)d_in[11];
    const float* w2  = (const float*)d_in[12];
    const float* b2  = (const float*)d_in[13];
    const float* lt  = (const float*)d_in[14];
    const float* onw = (const float*)d_in[15];
    const float* Wo  = (const float*)d_in[16];
    float* out = (float*)d_out;

    void* p;
    float *qkv, *mlp;
    __half *wh, *w1h, *woh, *xh, *gh;
    cudaGetSymbolAddress(&p, g_qkv); qkv = (float*)p;
    cudaGetSymbolAddress(&p, g_mlp); mlp = (float*)p;
    cudaGetSymbolAddress(&p, g_wh);  wh = (__half*)p;
    cudaGetSymbolAddress(&p, g_w1h); w1h = (__half*)p;
    cudaGetSymbolAddress(&p, g_woh); woh = (__half*)p;
    cudaGetSymbolAddress(&p, g_xh);  xh = (__half*)p;
    cudaGetSymbolAddress(&p, g_gh);  gh = (__half*)p;

    static int attr_done = 0;
    if (!attr_done) {
        cudaFuncSetAttribute(gemm_bf, cudaFuncAttributeMaxDynamicSharedMemorySize,
                             2 * STAGE_HALVES * (int)sizeof(__half));
        cudaFuncSetAttribute(precomp_kernel, cudaFuncAttributeMaxDynamicSharedMemorySize,
                             (4 * 32 * RS + 2048) * (int)sizeof(float));
        cudaFuncSetAttribute(scan_kernel, cudaFuncAttributeMaxDynamicSharedMemorySize,
                             SC_SMEM);
        attr_done = 1;
    }

    dim3 thr(256);
    dim3 wb(32, 8);
    int gsm = 2 * STAGE_HALVES * (int)sizeof(__half);

    split_kernel<<<R_ * H_ / 256, thr>>>(x, xh, R_ * H_);
    wconv3_kernel<<<dim3(32, 32, 3), wb>>>(Wq, Wk, Wv);
    beta_kernel<<<R_ / 4, 128>>>(x, Wb);
    // QKV: single-pass fp16
    gemm_bf<<<dim3(3 * H_ / 128, R_ / 128), thr, gsm>>>(xh, nullptr, wh, nullptr, qkv,
                                                        R_, 3 * H_, H_, 0);
    conv_v_kernel<<<R_ * H_ / 256, thr>>>(cv);
    wconv_kernel<<<dim3(MLPH_ / 32, GIN_ / 32), wb>>>(w1, w1h, GIN_, MLPH_);
    wconv_kernel<<<dim3(32, 32), wb>>>(Wo, woh, H_, H_);
    // precomp with fused q/k conv+silu
    precomp_kernel<<<B_ * NH_ * NCH_, thr,
                     (4 * 32 * RS + 2048) * sizeof(float)>>>(cq, ck);
    scan_kernel<<<128, 256, SC_SMEM>>>();
    fir_kernel<<<dim3(H_ / 64, B_ * L_ / 32), thr>>>(fsw, flw);
    gate_kernel<<<R_, thr>>>(x);
    // MLP1: single-pass fp16
    gemm_bf<<<dim3(MLPH_ / 128, R_ / 128), thr, gsm>>>(gh, nullptr, w1h, b1, mlp,
                                                       R_, MLPH_, GIN_, 1);
    mlp2_kernel<<<R_, 128>>>(w2, b2);
    combine_kernel<<<R_, thr>>>(lt, onw);
    // out-proj: single-pass fp16
    gemm_bf<<<dim3(H_ / 128, R_ / 128), thr, gsm>>>(xh, nullptr, woh, nullptr, out,
                                                    R_, H_, H_, 0);
}

// round 15
// speedup vs baseline: 1.0124x; 1.0124x over previous
#include <cuda_runtime.h>
#include <cuda_bf16.h>
#include <cuda_fp16.h>
#include <stdint.h>
#include <math.h>

#define B_   2
#define L_   2048
#define H_   1024
#define NH_  4
#define R_   (B_ * L_)       // 4096 rows
#define NCH_ 64              // chunks of 32 per sequence
#define GIN_ 1056
#define MLPH_ 2048

// ---------------- scratch ----------------
__device__ __align__(128) float g_qkv[(size_t)R_ * 3 * H_];
__device__ __align__(128) float g_qp[R_ * H_];     // u (fp32)
__device__ __align__(128) float g_vp[R_ * H_];     // delta_out
__device__ __align__(128) float g_q[R_ * H_];      // conv+silu q
__device__ __align__(128) float g_k[R_ * H_];      // conv+silu k
__device__ __align__(128) float g_v[R_ * H_];      // conv+silu v
__device__ __align__(128) float g_beta[R_ * NH_];
__device__ __align__(128) float g_fs[R_ * H_];
__device__ __align__(128) float g_fl[R_ * H_];
__device__ __align__(128) float g_mlp[(size_t)R_ * MLPH_];
__device__ __align__(128) float g_logits[R_ * 16];

// fp16 tiles for the scan (emitted by precomp; A-side single precision)
__device__ __align__(128) __half g_tq[R_ * H_];
__device__ __align__(128) __half g_tw[R_ * H_];
__device__ __align__(128) __half g_tkt[(size_t)B_*NH_*NCH_*8192];   // kT [bh][n][256][32]
__device__ __align__(128) __half g_ta[(size_t)B_*NH_*NCH_*1024];    // attn [bh][n][32][32]

// fp16 weights [N][K] (QKV packed: 3072 x 1024)
__device__ __align__(128) __half g_wh[3 * H_ * H_];
__device__ __align__(128) __half g_w1h[MLPH_ * GIN_];
__device__ __align__(128) __half g_woh[H_ * H_];
// fp16 activations
__device__ __align__(128) __half g_xh[R_ * H_];   // x, later oc
__device__ __align__(128) __half g_gh[(size_t)R_ * GIN_];

// ---------------- asm helpers ----------------
__device__ __forceinline__ void cpa16(uint32_t dst, const void* src) {
    asm volatile("cp.async.cg.shared.global [%0], [%1], 16;" :: "r"(dst), "l"(src));
}
#define CPA_COMMIT asm volatile("cp.async.commit_group;")
#define SMEMU32(p) ((uint32_t)__cvta_generic_to_shared(p))

#define MMAH16816(d, a, b0, b1) \
  asm volatile("mma.sync.aligned.m16n8k16.row.col.f32.f16.f16.f32 " \
    "{%0,%1,%2,%3}, {%4,%5,%6,%7}, {%8,%9}, {%0,%1,%2,%3};" \
    : "+f"(d[0]), "+f"(d[1]), "+f"(d[2]), "+f"(d[3]) \
    : "r"(a[0]), "r"(a[1]), "r"(a[2]), "r"(a[3]), "r"(b0), "r"(b1))

#define LDSM4(r0, r1, r2, r3, addr) \
  asm volatile("ldmatrix.sync.aligned.m8n8.x4.shared.b16 {%0,%1,%2,%3}, [%4];" \
    : "=r"(r0), "=r"(r1), "=r"(r2), "=r"(r3) : "r"(addr))

// ---------------- elementwise fp32 -> fp16 cast ----------------
__global__ void split_kernel(const float* __restrict__ A,
                             __half* __restrict__ Ah, int n)
{
    int i = blockIdx.x * 256 + threadIdx.x;
    if (i < n) Ah[i] = __float2half(A[i]);
}

// ---------------- weight transpose to fp16 [N][K] ----------------
__global__ void wconv_kernel(const float* __restrict__ W,
                             __half* __restrict__ Th, int K, int N)
{
    __shared__ float t[32][33];
    int k0 = blockIdx.y * 32, n0 = blockIdx.x * 32;
    int tx = threadIdx.x, ty = threadIdx.y;
    for (int i = ty; i < 32; i += 8)
        t[i][tx] = W[(size_t)(k0 + i) * N + n0 + tx];
    __syncthreads();
    for (int i = ty; i < 32; i += 8)
        Th[(size_t)(n0 + i) * K + k0 + tx] = __float2half(t[tx][i]);
}

__global__ void wconv3_kernel(const float* __restrict__ Wq,
                              const float* __restrict__ Wk,
                              const float* __restrict__ Wv)
{
    __shared__ float t[32][33];
    int z = blockIdx.z;
    const float* W = (z == 0) ? Wq : (z == 1) ? Wk : Wv;
    int k0 = blockIdx.y * 32, n0 = blockIdx.x * 32;
    int tx = threadIdx.x, ty = threadIdx.y;
    for (int i = ty; i < 32; i += 8)
        t[i][tx] = W[(size_t)(k0 + i) * H_ + n0 + tx];
    __syncthreads();
    size_t base = (size_t)z * H_ * H_;
    for (int i = ty; i < 32; i += 8)
        g_wh[base + (size_t)(n0 + i) * H_ + k0 + tx] = __float2half(t[tx][i]);
}

// ---------------- fp16 tensor-core GEMM ----------------
#define ASTR 40
#define STAGE_HALVES (3 * 128 * ASTR)

__global__ __launch_bounds__(256) void gemm_bf(
    const __half* __restrict__ Ahg, const __half* __restrict__ Alg,
    const __half* __restrict__ Bg,
    const float* __restrict__ bias, float* __restrict__ C,
    int M, int N, int K, int act)
{
    extern __shared__ __half smh[];
    int tid = threadIdx.x;
    int row0 = blockIdx.y * 128, col0 = blockIdx.x * 128;
    int wid = tid >> 5, lane = tid & 31;
    int wm = (wid >> 1) * 32, wn = (wid & 1) * 64;
    int g = lane >> 2, t = lane & 3;
    int lr = lane & 7, seg = lane >> 3;
    bool two = (Alg != nullptr);

    float acc[2][8][4];
#pragma unroll
    for (int i = 0; i < 2; i++)
#pragma unroll
        for (int j = 0; j < 8; j++)
#pragma unroll
            for (int q = 0; q < 4; q++) acc[i][j][q] = 0.f;

    const __half* gsrc[3] = {Ahg, Alg, Bg};
    int gr0[3] = {row0, row0, col0};

    auto load_stage = [&](int s, int k0) {
        __half* sp = smh + s * STAGE_HALVES;
#pragma unroll
        for (int a = 0; a < 3; a++) {
            if (a == 1 && !two) continue;
#pragma unroll
            for (int q = 0; q < 2; q++) {
                int c = tid * 2 + q;
                int r = c >> 2, sg = c & 3;
                uint32_t d = SMEMU32(sp + a * 128 * ASTR + r * ASTR + sg * 8);
                cpa16(d, gsrc[a] + (size_t)(gr0[a] + r) * K + k0 + sg * 8);
            }
        }
        CPA_COMMIT;
    };

    load_stage(0, 0);
    int nk = K / 32;
    for (int ki = 0; ki < nk; ki++) {
        if (ki + 1 < nk) {
            load_stage((ki + 1) & 1, (ki + 1) * 32);
            asm volatile("cp.async.wait_group 1;");
        } else {
            asm volatile("cp.async.wait_group 0;");
        }
        __syncthreads();
        __half* sp = smh + (ki & 1) * STAGE_HALVES;
        __half* Ah = sp;
        __half* Al = sp + 128 * ASTR;
        __half* Bs = sp + 2 * 128 * ASTR;
#pragma unroll
        for (int ks = 0; ks < 2; ks++) {
            int ko = ks * 16;
            int arow = wm + lr + ((seg & 1) << 3);
            int acol = ko + ((seg >> 1) << 3);
            uint32_t afh[2][4], afl[2][4];
#pragma unroll
            for (int mi = 0; mi < 2; mi++) {
                LDSM4(afh[mi][0], afh[mi][1], afh[mi][2], afh[mi][3],
                      SMEMU32(&Ah[(arow + mi * 16) * ASTR + acol]));
                if (two)
                    LDSM4(afl[mi][0], afl[mi][1], afl[mi][2], afl[mi][3],
                          SMEMU32(&Al[(arow + mi * 16) * ASTR + acol]));
            }
            int brow = wn + lr + ((seg >> 1) << 3);
            int bcol = ko + ((seg & 1) << 3);
            uint32_t b4[4][4];
#pragma unroll
            for (int nip = 0; nip < 4; nip++)
                LDSM4(b4[nip][0], b4[nip][1], b4[nip][2], b4[nip][3],
                      SMEMU32(&Bs[(brow + nip * 16) * ASTR + bcol]));
#pragma unroll
            for (int ni = 0; ni < 8; ni++) {
                uint32_t b0 = b4[ni >> 1][(ni & 1) * 2];
                uint32_t b1 = b4[ni >> 1][(ni & 1) * 2 + 1];
                MMAH16816(acc[0][ni], afh[0], b0, b1);
                MMAH16816(acc[1][ni], afh[1], b0, b1);
            }
            if (two) {
#pragma unroll
                for (int ni = 0; ni < 8; ni++) {
                    uint32_t b0 = b4[ni >> 1][(ni & 1) * 2];
                    uint32_t b1 = b4[ni >> 1][(ni & 1) * 2 + 1];
                    MMAH16816(acc[0][ni], afl[0], b0, b1);
                    MMAH16816(acc[1][ni], afl[1], b0, b1);
                }
            }
        }
        __syncthreads();
    }

#pragma unroll
    for (int mi = 0; mi < 2; mi++)
#pragma unroll
        for (int ni = 0; ni < 8; ni++) {
            int r = row0 + wm + mi * 16 + g;
            int c = col0 + wn + ni * 8 + 2 * t;
            float v[4];
#pragma unroll
            for (int q = 0; q < 4; q++) {
                float x = acc[mi][ni][q];
                if (bias) x += bias[c + (q & 1)];
                if (act == 1) x = 0.5f * x * (1.f + erff(x * 0.70710678118654752f));
                v[q] = x;
            }
            *(float2*)(C + (size_t)r * N + c)       = make_float2(v[0], v[1]);
            *(float2*)(C + (size_t)(r + 8) * N + c) = make_float2(v[2], v[3]);
        }
}

// ---------------- beta (float4 vectorized) ----------------
__global__ void beta_kernel(const float* __restrict__ x, const float* __restrict__ Wb)
{
    int r = blockIdx.x * 4 + (threadIdx.x >> 5);
    int lane = threadIdx.x & 31;
    float acc0 = 0, acc1 = 0, acc2 = 0, acc3 = 0;
    const float* xr = x + (size_t)r * H_;
    for (int kk = lane * 4; kk < H_; kk += 128) {
        float4 xv = *(const float4*)(xr + kk);
#pragma unroll
        for (int e = 0; e < 4; e++) {
            float xs = (e == 0) ? xv.x : (e == 1) ? xv.y : (e == 2) ? xv.z : xv.w;
            float4 w = *(const float4*)(Wb + (kk + e) * 4);
            acc0 += xs * w.x; acc1 += xs * w.y; acc2 += xs * w.z; acc3 += xs * w.w;
        }
    }
#pragma unroll
    for (int off = 16; off; off >>= 1) {
        acc0 += __shfl_down_sync(~0u, acc0, off);
        acc1 += __shfl_down_sync(~0u, acc1, off);
        acc2 += __shfl_down_sync(~0u, acc2, off);
        acc3 += __shfl_down_sync(~0u, acc3, off);
    }
    if (lane == 0) {
        g_beta[r * 4 + 0] = 1.f / (1.f + expf(-acc0));
        g_beta[r * 4 + 1] = 1.f / (1.f + expf(-acc1));
        g_beta[r * 4 + 2] = 1.f / (1.f + expf(-acc2));
        g_beta[r * 4 + 3] = 1.f / (1.f + expf(-acc3));
    }
}

// ---------------- fused causal conv K=4 + silu (q,k,v one launch) ----------------
__global__ void conv3_kernel(const float* __restrict__ cq,
                             const float* __restrict__ ck,
                             const float* __restrict__ cv)
{
    int z = blockIdx.y;
    const float* w = (z == 0) ? cq : (z == 1) ? ck : cv;
    float* dst = (z == 0) ? g_q : (z == 1) ? g_k : g_v;
    int srcOff = z * H_;

    int tid = blockIdx.x * blockDim.x + threadIdx.x;
    int c = tid & (H_ - 1);
    int r = tid >> 10;
    int b = r >> 11;
    int l = r & (L_ - 1);
    const float* wc = w + c * 4;
    float acc = 0.f;
#pragma unroll
    for (int j = 0; j < 4; j++) {
        int ll = l - 3 + j;
        if (ll >= 0) acc += g_qkv[(size_t)(b * L_ + ll) * 3 * H_ + srcOff + c] * wc[j];
    }
    dst[tid] = acc / (1.f + expf(-acc));
}

// ---------------- delta precompute ----------------
#define RS 260
__global__ __launch_bounds__(256) void precomp_kernel()
{
    extern __shared__ float sm[];
    float* Qs = sm;
    float* Ks = Qs + 32 * RS;
    float* KB = Ks + 32 * RS;
    float* VB = KB + 32 * RS;
    float* Am = VB + 32 * RS;
    float* Tm = Am + 1024;
    __shared__ float rbeta[32], qn_s[32], kn_s[32];

    int bhn = blockIdx.x;
    int n = bhn % NCH_; int bh = bhn / NCH_;
    int b = bh >> 2, h = bh & 3;
    int l0 = n * 32;
    int tid = threadIdx.x, wi = tid >> 5, lane = tid & 31;

    for (int e = tid; e < 8192; e += 256) {
        int i = e >> 8, d = e & 255;
        size_t gi = ((size_t)(b * L_ + l0 + i) << 10) + h * 256 + d;
        Qs[i * RS + d] = g_q[gi];
        Ks[i * RS + d] = g_k[gi];
    }
    if (tid < 32) rbeta[tid] = g_beta[(b * L_ + l0 + tid) * 4 + h];
    __syncthreads();

    for (int rr = wi; rr < 32; rr += 8) {
        float sq = 0, sk = 0;
        for (int d = lane; d < 256; d += 32) {
            float a = Qs[rr * RS + d]; sq += a * a;
            float c = Ks[rr * RS + d]; sk += c * c;
        }
#pragma unroll
        for (int off = 16; off; off >>= 1) {
            sq += __shfl_down_sync(~0u, sq, off);
            sk += __shfl_down_sync(~0u, sk, off);
        }
        if (lane == 0) { qn_s[rr] = rsqrtf(sq + 1e-6f); kn_s[rr] = rsqrtf(sk + 1e-6f); }
    }
    __syncthreads();

    for (int e = tid; e < 8192; e += 256) {
        int i = e >> 8, d = e & 255;
        size_t gi = ((size_t)(b * L_ + l0 + i) << 10) + h * 256 + d;
        float qv = Qs[i * RS + d] * qn_s[i]; Qs[i * RS + d] = qv;
        float kv = Ks[i * RS + d] * kn_s[i]; Ks[i * RS + d] = kv;
        KB[i * RS + d] = kv * rbeta[i];
        VB[i * RS + d] = g_v[gi] * rbeta[i];
        g_tq[gi] = __float2half(qv);
    }
    __syncthreads();

    {
        size_t ckb = ((size_t)bh * NCH_ + n) * 8192;
        for (int e4 = tid; e4 < 2048; e4 += 256) {
            int i = e4 & 31, d0 = (e4 >> 5) * 4;
            float4 kv = *(const float4*)(Ks + i * RS + d0);
            g_tkt[ckb + (size_t)(d0 + 0) * 32 + i] = __float2half(kv.x);
            g_tkt[ckb + (size_t)(d0 + 1) * 32 + i] = __float2half(kv.y);
            g_tkt[ckb + (size_t)(d0 + 2) * 32 + i] = __float2half(kv.z);
            g_tkt[ckb + (size_t)(d0 + 3) * 32 + i] = __float2half(kv.w);
        }
    }

    for (int e = tid; e < 1024; e += 256) {
        int i = e >> 5, j = e & 31;
        float s = 0.f;
        if (j < i) {
            const float4* a = (const float4*)(KB + i * RS);
            const float4* c = (const float4*)(Ks + j * RS);
#pragma unroll 8
            for (int d = 0; d < 64; d++) {
                float4 av = a[d], cv = c[d];
                s += av.x * cv.x + av.y * cv.y + av.z * cv.z + av.w * cv.w;
            }
        }
        Am[e] = s;
    }
    __syncthreads();

    if (wi == 0) {
        int j = lane;
        for (int i = 0; i < 32; i++) {
            float val = (i == j) ? 1.f : 0.f;
            for (int m = j; m < i; m++) val -= Am[i * 32 + m] * Tm[m * 32 + j];
            Tm[i * 32 + j] = val;
            __syncwarp();
        }
    }
    __syncthreads();

    {
        size_t ab = ((size_t)bh * NCH_ + n) * 1024;
        for (int e = tid; e < 1024; e += 256) {
            int i = e >> 5, j = e & 31;
            float s = 0.f;
            if (j <= i) {
                const float4* a = (const float4*)(Qs + i * RS);
                const float4* c = (const float4*)(Ks + j * RS);
#pragma unroll 8
                for (int d = 0; d < 64; d++) {
                    float4 av = a[d], cv = c[d];
                    s += av.x * cv.x + av.y * cv.y + av.z * cv.z + av.w * cv.w;
                }
            }
            g_ta[ab + e] = __float2half(s);
        }
    }

    for (int e4 = tid; e4 < 2048; e4 += 256) {
        int i = e4 >> 6, d0 = (e4 & 63) * 4;
        float4 su = make_float4(0.f, 0.f, 0.f, 0.f);
        float4 sw = make_float4(0.f, 0.f, 0.f, 0.f);
        const float* tr = Tm + i * 32;
#pragma unroll
        for (int m = 0; m < 32; m++) {
            float t = tr[m];
            float4 vb = *(const float4*)(VB + m * RS + d0);
            float4 kb = *(const float4*)(KB + m * RS + d0);
            su.x += t * vb.x; su.y += t * vb.y; su.z += t * vb.z; su.w += t * vb.w;
            sw.x += t * kb.x; sw.y += t * kb.y; sw.z += t * kb.z; sw.w += t * kb.w;
        }
        size_t gi = ((size_t)(b * L_ + l0 + i) << 10) + h * 256 + d0;
        *(float4*)(g_qp + gi) = su;
        __half2* wp = (__half2*)(g_tw + gi);
        wp[0] = __floats2half2_rn(sw.x, sw.y);
        wp[1] = __floats2half2_rn(sw.z, sw.w);
    }
}

// ---------------- tensor-core scan: KT double-buffered ----------------
// smem map (bytes):
//   0      S fp32 [256][16]          (16384)
//   16384  U2 fp32 [32][16]          (2048)
//   18432  SbTh fp16 [16][264]       (8448)
//   26880  SbTl fp16 [16][264]       (8448)
//   35328  U2Th fp16 [16][40]        (1280)
//   36608  U2Tl fp16 [16][40]        (1280)
//   37888  KT0 fp16 [256][40]        (20480)
//   58368  KT1 fp16 [256][40]        (20480)
//   78848  stage0 (38400)
//   117248 stage1 (38400)
#define SC_SMEM 155648
#define STG_OFF 78848
#define STG_SZ  38400

__global__ __launch_bounds__(256) void scan_kernel()
{
    extern __shared__ char sc[];
    float* S  = (float*)sc;
    float* U2 = (float*)(sc + 16384);
    __half* SbTh = (__half*)(sc + 18432);
    __half* SbTl = (__half*)(sc + 26880);
    __half* U2Th = (__half*)(sc + 35328);
    __half* U2Tl = (__half*)(sc + 36608);
    __half* KT0  = (__half*)(sc + 37888);

    int blk = blockIdx.x;
    int bh = blk >> 4, slice = blk & 15;
    int b = bh >> 2, h = bh & 3;
    int tid = threadIdx.x;
    int wi = tid >> 5, lane = tid & 31;
    int g = lane >> 2, t4 = lane & 3;
    int dvb = h * 256 + slice * 16;

    for (int e = tid; e < 4096; e += 256) S[e] = 0.f;
    for (int e = tid; e < 16 * 264; e += 256) {
        SbTh[e] = __float2half(0.f);
        SbTl[e] = __float2half(0.f);
    }

    auto issue_main = [&](int n, int buf) {
        char* sp = sc + STG_OFF + buf * STG_SZ;
        __half* Wt = (__half*)sp;
        __half* Qt = (__half*)(sp + 16896);
        float*  Uf = (float*)(sp + 33792);
        __half* At = (__half*)(sp + 35840);
        int row0 = b * L_ + n * 32;
#pragma unroll
        for (int it = 0; it < 8; it++) {
            int c = tid + it * 256;
            int a = c >> 10, rem = c & 1023;
            int r = rem >> 5, s = rem & 31;
            __half* dst = a ? Qt : Wt;
            const __half* src = a ? g_tq : g_tw;
            cpa16(SMEMU32(dst + r * 264 + s * 8),
                  src + ((size_t)(row0 + r) << 10) + h * 256 + s * 8);
        }
        if (tid < 128) {
            int r = tid >> 2, s = tid & 3;
            cpa16(SMEMU32(Uf + r * 16 + s * 4),
                  g_qp + ((size_t)(row0 + r) << 10) + dvb + s * 4);
        }
        if (tid < 128) {
            int r = tid >> 2, s = tid & 3;
            cpa16(SMEMU32(At + r * 40 + s * 8),
                  g_ta + ((size_t)bh * NCH_ + n) * 1024 + r * 32 + s * 8);
        }
        // kT into the same buffer parity (double-buffered now)
        {
            size_t base = ((size_t)bh * NCH_ + n) * 8192;
            __half* KT = KT0 + buf * 10240;
#pragma unroll
            for (int it = 0; it < 4; it++) {
                int c = tid + it * 256;
                int r = c >> 2, s = c & 3;
                cpa16(SMEMU32(KT + r * 40 + s * 8), g_tkt + base + r * 32 + s * 8);
            }
        }
        CPA_COMMIT;
    };

    issue_main(0, 0);
    int buf = 0;

#pragma unroll 1
    for (int n = 0; n < NCH_; n++) {
        asm volatile("cp.async.wait_group 0;");
        if (n + 1 < NCH_) issue_main(n + 1, buf ^ 1);
        __syncthreads();

        char* sp = sc + STG_OFF + buf * STG_SZ;
        const __half* Wt = (const __half*)sp;
        const __half* Qt = (const __half*)(sp + 16896);
        const float*  Uf = (const float*)(sp + 33792);
        const __half* At = (const __half*)(sp + 35840);
        const __half* KT = KT0 + buf * 10240;

        float c0[4] = {0,0,0,0}, c1[4] = {0,0,0,0};
        int w4 = wi & 3;
        int m0 = (w4 >> 1) * 16, n0 = (w4 & 1) * 8;
        const __half* Am_ = (wi < 4) ? Wt : Qt;
#pragma unroll
        for (int kk = 0; kk < 16; kk++) {
            int ka = kk * 16 + 2 * t4;
            uint32_t ah[4];
            ah[0] = *(const uint32_t*)&Am_[(m0 + g) * 264 + ka];
            ah[1] = *(const uint32_t*)&Am_[(m0 + 8 + g) * 264 + ka];
            ah[2] = *(const uint32_t*)&Am_[(m0 + g) * 264 + ka + 8];
            ah[3] = *(const uint32_t*)&Am_[(m0 + 8 + g) * 264 + ka + 8];
            uint32_t bh0 = *(const uint32_t*)&SbTh[(n0 + g) * 264 + ka];
            uint32_t bh1 = *(const uint32_t*)&SbTh[(n0 + g) * 264 + ka + 8];
            uint32_t bl0 = *(const uint32_t*)&SbTl[(n0 + g) * 264 + ka];
            uint32_t bl1 = *(const uint32_t*)&SbTl[(n0 + g) * 264 + ka + 8];
            MMAH16816(c0, ah, bh0, bh1);
            MMAH16816(c1, ah, bl0, bl1);
        }
        if (wi < 4) {
            U2[(m0 + g) * 16 + n0 + 2 * t4]         = Uf[(m0 + g) * 16 + n0 + 2 * t4]         - (c0[0] + c1[0]);
            U2[(m0 + g) * 16 + n0 + 2 * t4 + 1]     = Uf[(m0 + g) * 16 + n0 + 2 * t4 + 1]     - (c0[1] + c1[1]);
            U2[(m0 + 8 + g) * 16 + n0 + 2 * t4]     = Uf[(m0 + 8 + g) * 16 + n0 + 2 * t4]     - (c0[2] + c1[2]);
            U2[(m0 + 8 + g) * 16 + n0 + 2 * t4 + 1] = Uf[(m0 + 8 + g) * 16 + n0 + 2 * t4 + 1] - (c0[3] + c1[3]);
        }
        __syncthreads();

#pragma unroll
        for (int q2 = 0; q2 < 2; q2++) {
            int e = tid + q2 * 256;
            int i2 = e >> 4, j2 = e & 15;
            float v = U2[i2 * 16 + j2];
            __half hv = __float2half(v);
            U2Th[j2 * 40 + i2] = hv;
            U2Tl[j2 * 40 + i2] = __float2half(v - __half2float(hv));
        }
        __syncthreads();

        if (wi >= 4) {
#pragma unroll
            for (int kk = 0; kk < 2; kk++) {
                int ka = kk * 16 + 2 * t4;
                uint32_t ah[4];
                ah[0] = *(const uint32_t*)&At[(m0 + g) * 40 + ka];
                ah[1] = *(const uint32_t*)&At[(m0 + 8 + g) * 40 + ka];
                ah[2] = *(const uint32_t*)&At[(m0 + g) * 40 + ka + 8];
                ah[3] = *(const uint32_t*)&At[(m0 + 8 + g) * 40 + ka + 8];
                uint32_t bh0 = *(const uint32_t*)&U2Th[(n0 + g) * 40 + ka];
                uint32_t bh1 = *(const uint32_t*)&U2Th[(n0 + g) * 40 + ka + 8];
                uint32_t bl0 = *(const uint32_t*)&U2Tl[(n0 + g) * 40 + ka];
                uint32_t bl1 = *(const uint32_t*)&U2Tl[(n0 + g) * 40 + ka + 8];
                MMAH16816(c0, ah, bh0, bh1);
                MMAH16816(c1, ah, bl0, bl1);
            }
            size_t ob = ((size_t)(b * L_ + n * 32) << 10) + dvb + n0 + 2 * t4;
            *(float2*)(g_vp + ob + ((size_t)(m0 + g) << 10)) =
                make_float2(c0[0] + c1[0], c0[1] + c1[1]);
            *(float2*)(g_vp + ob + ((size_t)(m0 + 8 + g) << 10)) =
                make_float2(c0[2] + c1[2], c0[3] + c1[3]);
        }

#pragma unroll
        for (int mm = 0; mm < 2; mm++)
#pragma unroll
        for (int nn = 0; nn < 2; nn++) {
            int m0p = (wi * 2 + mm) * 16, n0p = nn * 8;
            float d0[4];
            float2 s01 = *(float2*)(S + (m0p + g) * 16 + n0p + 2 * t4);
            float2 s23 = *(float2*)(S + (m0p + 8 + g) * 16 + n0p + 2 * t4);
            d0[0] = s01.x; d0[1] = s01.y; d0[2] = s23.x; d0[3] = s23.y;
#pragma unroll
            for (int kk = 0; kk < 2; kk++) {
                int ka = kk * 16 + 2 * t4;
                uint32_t ah[4];
                ah[0] = *(const uint32_t*)&KT[(m0p + g) * 40 + ka];
                ah[1] = *(const uint32_t*)&KT[(m0p + 8 + g) * 40 + ka];
                ah[2] = *(const uint32_t*)&KT[(m0p + g) * 40 + ka + 8];
                ah[3] = *(const uint32_t*)&KT[(m0p + 8 + g) * 40 + ka + 8];
                uint32_t bh0 = *(const uint32_t*)&U2Th[(n0p + g) * 40 + ka];
                uint32_t bh1 = *(const uint32_t*)&U2Th[(n0p + g) * 40 + ka + 8];
                uint32_t bl0 = *(const uint32_t*)&U2Tl[(n0p + g) * 40 + ka];
                uint32_t bl1 = *(const uint32_t*)&U2Tl[(n0p + g) * 40 + ka + 8];
                MMAH16816(d0, ah, bh0, bh1);
                MMAH16816(d0, ah, bl0, bl1);
            }
            *(float2*)(S + (m0p + g) * 16 + n0p + 2 * t4)     = make_float2(d0[0], d0[1]);
            *(float2*)(S + (m0p + 8 + g) * 16 + n0p + 2 * t4) = make_float2(d0[2], d0[3]);
        }
        __syncthreads();

        {
            int j = tid & 15, kb = tid >> 4;
#pragma unroll
            for (int m = 0; m < 16; m++) {
                int k = kb + m * 16;
                float v = S[k * 16 + j];
                __half hv = __float2half(v);
                SbTh[j * 264 + k] = hv;
                SbTl[j * 264 + k] = __float2half(v - __half2float(hv));
            }
        }
        __syncthreads();
        buf ^= 1;
    }
}

// ---------------- FIR convs ----------------
__global__ __launch_bounds__(256) void fir_kernel(const float* __restrict__ ws,
                                                  const float* __restrict__ wl)
{
    __shared__ float vt[94][64];
    __shared__ float wls[64 * 63];
    __shared__ float wss[64 * 3];
    int cb = blockIdx.x;
    int lb = blockIdx.y;
    int b = lb >> 6;
    int l0 = (lb & 63) * 32;
    int c0 = cb * 64;
    int tid = threadIdx.x;

    for (int e = tid; e < 94 * 64; e += 256) {
        int rr = e >> 6, cc = e & 63;
        int l = l0 - 62 + rr;
        vt[rr][cc] = (l >= 0) ? g_v[((size_t)(b * L_ + l) << 10) + c0 + cc] : 0.f;
    }
    for (int e = tid; e < 64 * 63; e += 256) wls[e] = wl[(size_t)c0 * 63 + e];
    for (int e = tid; e < 64 * 3; e += 256)  wss[e] = ws[(size_t)c0 * 3 + e];
    __syncthreads();

    for (int e = tid; e < 32 * 64; e += 256) {
        int i = e >> 6, cc = e & 63;
        float aL = 0.f, aS = 0.f;
        const float* wlr = wls + cc * 63;
#pragma unroll 9
        for (int j = 0; j < 63; j++) aL += vt[i + j][cc] * wlr[j];
        const float* wsr = wss + cc * 3;
#pragma unroll
        for (int j = 0; j < 3; j++) aS += vt[i + 60 + j][cc] * wsr[j];
        size_t gi = ((size_t)(b * L_ + l0 + i) << 10) + c0 + cc;
        g_fl[gi] = aL;
        g_fs[gi] = aS;
    }
}

// ---------------- gate input: write fp16 directly ----------------
__global__ void gate_kernel(const float* __restrict__ x)
{
    __shared__ float stats[32];
    int r = blockIdx.x, tid = threadIdx.x;
    int wi = tid >> 5, lane = tid & 31;
    for (int p = wi; p < 16; p += 8) {
        int br = p >> 2, h = p & 3;
        const float* src = (br == 0 ? g_fs : br == 1 ? g_fl : br == 2 ? g_vp : g_v)
                           + ((size_t)r << 10) + h * 256;
        float s = 0, s2 = 0;
        for (int d = lane; d < 256; d += 32) { float t = src[d]; s += t; s2 += t * t; }
#pragma unroll
        for (int off = 16; off; off >>= 1) {
            s += __shfl_down_sync(~0u, s, off);
            s2 += __shfl_down_sync(~0u, s2, off);
        }
        if (lane == 0) {
            float mean = s * (1.f / 256.f);
            float var = s2 * (1.f / 256.f) - mean * mean;
            stats[br * 8 + h] = mean;
            stats[br * 8 + 4 + h] = sqrtf(fmaxf(var, 1e-6f));
        }
    }
    __syncthreads();
    const float* xr = x + (size_t)r * H_;
    size_t gb = (size_t)r * GIN_;
    for (int e = tid; e < GIN_; e += 256) {
        float v = (e < H_) ? xr[e] : stats[e - H_];
        g_gh[gb + e] = __float2half(v);
    }
}

// ---------------- MLP2 ----------------
__global__ void mlp2_kernel(const float* __restrict__ w2, const float* __restrict__ b2)
{
    int r = blockIdx.x, tid = threadIdx.x;
    float acc[16];
#pragma unroll
    for (int o = 0; o < 16; o++) acc[o] = 0.f;
    const float* hr = g_mlp + (size_t)r * MLPH_;
    for (int kk = tid; kk < MLPH_; kk += 128) {
        float hv = hr[kk];
        const float4* wr = (const float4*)(w2 + (size_t)kk * 16);
        float4 w0 = wr[0], w1 = wr[1], w2v = wr[2], w3 = wr[3];
        acc[0] += hv * w0.x; acc[1] += hv * w0.y; acc[2] += hv * w0.z; acc[3] += hv * w0.w;
        acc[4] += hv * w1.x; acc[5] += hv * w1.y; acc[6] += hv * w1.z; acc[7] += hv * w1.w;
        acc[8] += hv * w2v.x; acc[9] += hv * w2v.y; acc[10] += hv * w2v.z; acc[11] += hv * w2v.w;
        acc[12] += hv * w3.x; acc[13] += hv * w3.y; acc[14] += hv * w3.z; acc[15] += hv * w3.w;
    }
    __shared__ float part[4][16];
    int wi = tid >> 5, lane = tid & 31;
#pragma unroll
    for (int o = 0; o < 16; o++) {
        float v = acc[o];
#pragma unroll
        for (int off = 16; off; off >>= 1) v += __shfl_down_sync(~0u, v, off);
        if (lane == 0) part[wi][o] = v;
    }
    __syncthreads();
    if (tid < 16)
        g_logits[r * 16 + tid] =
            part[0][tid] + part[1][tid] + part[2][tid] + part[3][tid] + b2[tid];
}

// ---------------- combine + RMSNorm ----------------
__global__ void combine_kernel(const float* __restrict__ ltemp,
                               const float* __restrict__ onw)
{
    int r = blockIdx.x, tid = threadIdx.x;
    int wi = tid >> 5, lane = tid & 31;
    __shared__ float wsum[8];
    __shared__ float bcast;
    const float* lg = g_logits + r * 16;
#pragma unroll 1
    for (int h = 0; h < 4; h++) {
        float temp = log1pf(expf(ltemp[h])) + 1e-4f;
        float l0 = lg[h * 4 + 0] / temp, l1 = lg[h * 4 + 1] / temp;
        float l2 = lg[h * 4 + 2] / temp, l3 = lg[h * 4 + 3] / temp;
        float mx = fmaxf(fmaxf(l0, l1), fmaxf(l2, l3));
        float e0 = expf(l0 - mx), e1 = expf(l1 - mx), e2 = expf(l2 - mx), e3 = expf(l3 - mx);
        float inv = 1.f / (e0 + e1 + e2 + e3);
        size_t idx = ((size_t)r << 10) + h * 256 + tid;
        float ov = (e0 * g_fs[idx] + e1 * g_fl[idx] + e2 * g_vp[idx] + e3 * g_v[idx]) * inv;
        float sq = ov * ov;
#pragma unroll
        for (int off = 16; off; off >>= 1) sq += __shfl_down_sync(~0u, sq, off);
        if (lane == 0) wsum[wi] = sq;
        __syncthreads();
        if (tid == 0) {
            float s = 0.f;
#pragma unroll
            for (int q = 0; q < 8; q++) s += wsum[q];
            bcast = rsqrtf(s * (1.f / 256.f) + 1e-5f);
        }
        __syncthreads();
        float val = ov * bcast * onw[tid];
        g_xh[idx] = __float2half(val);
        __syncthreads();
    }
}

// ---------------- launch ----------------
extern "C" void kernel_launch(void* const* d_in, const int* in_sizes, int n_in,
                              void* d_out, int out_size)
{
    const float* x   = (const float*)d_in[0];
    const float* Wq  = (const float*)d_in[1];
    const float* Wk  = (const float*)d_in[2];
    const float* Wv  = (const float*)d_in[3];
    const float* Wb  = (const float*)d_in[4];
    const float* cq  = (const float*)d_in[5];
    const float* ck  = (const float*)d_in[6];
    const float* cv  = (const float*)d_in[7];
    const float* fsw = (const float*)d_in[8];
    const float* flw = (const float*)d_in[9];
    const float* w1  = (const float*)d_in[10];
    const float* b1  = (const float*)d_in[11];
    const float* w2  = (const float*)d_in[12];
    const float* b2  = (const float*)d_in[13];
    const float* lt  = (const float*)d_in[14];
    const float* onw = (const float*)d_in[15];
    const float* Wo  = (const float*)d_in[16];
    float* out = (float*)d_out;

    void* p;
    float *qkv, *mlp;
    __half *wh, *w1h, *woh, *xh, *gh;
    cudaGetSymbolAddress(&p, g_qkv); qkv = (float*)p;
    cudaGetSymbolAddress(&p, g_mlp); mlp = (float*)p;
    cudaGetSymbolAddress(&p, g_wh);  wh = (__half*)p;
    cudaGetSymbolAddress(&p, g_w1h); w1h = (__half*)p;
    cudaGetSymbolAddress(&p, g_woh); woh = (__half*)p;
    cudaGetSymbolAddress(&p, g_xh);  xh = (__half*)p;
    cudaGetSymbolAddress(&p, g_gh);  gh = (__half*)p;

    static int attr_done = 0;
    if (!attr_done) {
        cudaFuncSetAttribute(gemm_bf, cudaFuncAttributeMaxDynamicSharedMemorySize,
                             2 * STAGE_HALVES * (int)sizeof(__half));
        cudaFuncSetAttribute(precomp_kernel, cudaFuncAttributeMaxDynamicSharedMemorySize,
                             (4 * 32 * RS + 2048) * (int)sizeof(float));
        cudaFuncSetAttribute(scan_kernel, cudaFuncAttributeMaxDynamicSharedMemorySize,
                             SC_SMEM);
        attr_done = 1;
    }

    dim3 thr(256);
    dim3 wb(32, 8);
    int gsm = 2 * STAGE_HALVES * (int)sizeof(__half);

    split_kernel<<<R_ * H_ / 256, thr>>>(x, xh, R_ * H_);
    wconv3_kernel<<<dim3(32, 32, 3), wb>>>(Wq, Wk, Wv);
    beta_kernel<<<R_ / 4, 128>>>(x, Wb);
    // QKV: single-pass fp16
    gemm_bf<<<dim3(3 * H_ / 128, R_ / 128), thr, gsm>>>(xh, nullptr, wh, nullptr, qkv,
                                                        R_, 3 * H_, H_, 0);
    conv3_kernel<<<dim3(R_ * H_ / 256, 3), thr>>>(cq, ck, cv);
    wconv_kernel<<<dim3(MLPH_ / 32, GIN_ / 32), wb>>>(w1, w1h, GIN_, MLPH_);
    wconv_kernel<<<dim3(32, 32), wb>>>(Wo, woh, H_, H_);
    precomp_kernel<<<B_ * NH_ * NCH_, thr,
                     (4 * 32 * RS + 2048) * sizeof(float)>>>();
    scan_kernel<<<128, 256, SC_SMEM>>>();
    fir_kernel<<<dim3(H_ / 64, B_ * L_ / 32), thr>>>(fsw, flw);
    gate_kernel<<<R_, thr>>>(x);
    // MLP1: single-pass fp16
    gemm_bf<<<dim3(MLPH_ / 128, R_ / 128), thr, gsm>>>(gh, nullptr, w1h, b1, mlp,
                                                       R_, MLPH_, GIN_, 1);
    mlp2_kernel<<<R_, 128>>>(w2, b2);
    combine_kernel<<<R_, thr>>>(lt, onw);
    // out-proj: single-pass fp16
    gemm_bf<<<dim3(H_ / 128, R_ / 128), thr, gsm>>>(xh, nullptr, woh, nullptr, out,
                                                    R_, H_, H_, 0);
}

// round 16
// speedup vs baseline: 1.0494x; 1.0365x over previous
#include <cuda_runtime.h>
#include <cuda_bf16.h>
#include <cuda_fp16.h>
#include <stdint.h>
#include <math.h>

#define B_   2
#define L_   2048
#define H_   1024
#define NH_  4
#define R_   (B_ * L_)       // 4096 rows
#define NCH_ 64              // chunks of 32 per sequence
#define GIN_ 1056
#define MLPH_ 2048

// ---------------- scratch ----------------
__device__ __align__(128) float g_qkv[(size_t)R_ * 3 * H_];
__device__ __align__(128) float g_qp[R_ * H_];     // u (fp32)
__device__ __align__(128) float g_vp[R_ * H_];     // delta_out
__device__ __align__(128) float g_q[R_ * H_];      // conv+silu q
__device__ __align__(128) float g_k[R_ * H_];      // conv+silu k
__device__ __align__(128) float g_v[R_ * H_];      // conv+silu v
__device__ __align__(128) float g_beta[R_ * NH_];
__device__ __align__(128) float g_fs[R_ * H_];
__device__ __align__(128) float g_fl[R_ * H_];
__device__ __align__(128) float g_mlp[(size_t)R_ * MLPH_];

// fp16 tiles for the scan (emitted by precomp; A-side single precision)
__device__ __align__(128) __half g_tq[R_ * H_];
__device__ __align__(128) __half g_tw[R_ * H_];
__device__ __align__(128) __half g_tkt[(size_t)B_*NH_*NCH_*8192];   // kT [bh][n][256][32]
__device__ __align__(128) __half g_ta[(size_t)B_*NH_*NCH_*1024];    // attn [bh][n][32][32]

// fp16 weights [N][K] (QKV packed: 3072 x 1024)
__device__ __align__(128) __half g_wh[3 * H_ * H_];
__device__ __align__(128) __half g_w1h[MLPH_ * GIN_];
__device__ __align__(128) __half g_woh[H_ * H_];
// fp16 activations
__device__ __align__(128) __half g_xh[R_ * H_];   // x, later oc
__device__ __align__(128) __half g_gh[(size_t)R_ * GIN_];

// ---------------- asm helpers ----------------
__device__ __forceinline__ void cpa16(uint32_t dst, const void* src) {
    asm volatile("cp.async.cg.shared.global [%0], [%1], 16;" :: "r"(dst), "l"(src));
}
#define CPA_COMMIT asm volatile("cp.async.commit_group;")
#define SMEMU32(p) ((uint32_t)__cvta_generic_to_shared(p))

#define MMAH16816(d, a, b0, b1) \
  asm volatile("mma.sync.aligned.m16n8k16.row.col.f32.f16.f16.f32 " \
    "{%0,%1,%2,%3}, {%4,%5,%6,%7}, {%8,%9}, {%0,%1,%2,%3};" \
    : "+f"(d[0]), "+f"(d[1]), "+f"(d[2]), "+f"(d[3]) \
    : "r"(a[0]), "r"(a[1]), "r"(a[2]), "r"(a[3]), "r"(b0), "r"(b1))

#define LDSM4(r0, r1, r2, r3, addr) \
  asm volatile("ldmatrix.sync.aligned.m8n8.x4.shared.b16 {%0,%1,%2,%3}, [%4];" \
    : "=r"(r0), "=r"(r1), "=r"(r2), "=r"(r3) : "r"(addr))

// ---------------- merged prep: split + wconv3 + beta + wconv(w1) + wconv(Wo) -----
#define NB_SPLIT (R_ * H_ / 256)           // 16384
#define NB_WC3   3072
#define NB_BETA  (R_ / 8)                  // 512
#define NB_W1    (64 * 33)                 // 2112
#define NB_WO    1024
#define NB_PREP  (NB_SPLIT + NB_WC3 + NB_BETA + NB_W1 + NB_WO)

__global__ __launch_bounds__(256) void prep_kernel(
    const float* __restrict__ x,
    const float* __restrict__ Wq, const float* __restrict__ Wk,
    const float* __restrict__ Wv, const float* __restrict__ Wb,
    const float* __restrict__ w1, const float* __restrict__ Wo)
{
    __shared__ float t[32][33];
    int bid = blockIdx.x;
    int tid = threadIdx.x;

    if (bid < NB_SPLIT) {
        // split x -> fp16
        int i = bid * 256 + tid;
        g_xh[i] = __float2half(x[i]);
        return;
    }
    bid -= NB_SPLIT;
    if (bid < NB_WC3) {
        // QKV weight transpose [K][N]->[N][K] fp16, packed
        int z = bid >> 10, rem = bid & 1023;
        int k0 = (rem >> 5) * 32, n0 = (rem & 31) * 32;
        const float* W = (z == 0) ? Wq : (z == 1) ? Wk : Wv;
        int tx = tid & 31, ty = tid >> 5;
        for (int i = ty; i < 32; i += 8)
            t[i][tx] = W[(size_t)(k0 + i) * H_ + n0 + tx];
        __syncthreads();
        size_t base = (size_t)z * H_ * H_;
        for (int i = ty; i < 32; i += 8)
            g_wh[base + (size_t)(n0 + i) * H_ + k0 + tx] = __float2half(t[tx][i]);
        return;
    }
    bid -= NB_WC3;
    if (bid < NB_BETA) {
        // beta: 8 rows per block (one per warp)
        int r = bid * 8 + (tid >> 5);
        int lane = tid & 31;
        float acc0 = 0, acc1 = 0, acc2 = 0, acc3 = 0;
        const float* xr = x + (size_t)r * H_;
        for (int kk = lane * 4; kk < H_; kk += 128) {
            float4 xv = *(const float4*)(xr + kk);
#pragma unroll
            for (int e = 0; e < 4; e++) {
                float xs = (e == 0) ? xv.x : (e == 1) ? xv.y : (e == 2) ? xv.z : xv.w;
                float4 w = *(const float4*)(Wb + (kk + e) * 4);
                acc0 += xs * w.x; acc1 += xs * w.y; acc2 += xs * w.z; acc3 += xs * w.w;
            }
        }
#pragma unroll
        for (int off = 16; off; off >>= 1) {
            acc0 += __shfl_down_sync(~0u, acc0, off);
            acc1 += __shfl_down_sync(~0u, acc1, off);
            acc2 += __shfl_down_sync(~0u, acc2, off);
            acc3 += __shfl_down_sync(~0u, acc3, off);
        }
        if (lane == 0) {
            g_beta[r * 4 + 0] = 1.f / (1.f + expf(-acc0));
            g_beta[r * 4 + 1] = 1.f / (1.f + expf(-acc1));
            g_beta[r * 4 + 2] = 1.f / (1.f + expf(-acc2));
            g_beta[r * 4 + 3] = 1.f / (1.f + expf(-acc3));
        }
        return;
    }
    bid -= NB_BETA;
    if (bid < NB_W1) {
        // w1 transpose: [GIN][MLPH] -> [MLPH][GIN] fp16
        int n0 = (bid & 63) * 32, k0 = (bid >> 6) * 32;
        int tx = tid & 31, ty = tid >> 5;
        for (int i = ty; i < 32; i += 8)
            t[i][tx] = w1[(size_t)(k0 + i) * MLPH_ + n0 + tx];
        __syncthreads();
        for (int i = ty; i < 32; i += 8)
            g_w1h[(size_t)(n0 + i) * GIN_ + k0 + tx] = __float2half(t[tx][i]);
        return;
    }
    bid -= NB_W1;
    {
        // Wo transpose: [H][H] -> [H][H] fp16
        int n0 = (bid & 31) * 32, k0 = (bid >> 5) * 32;
        int tx = tid & 31, ty = tid >> 5;
        for (int i = ty; i < 32; i += 8)
            t[i][tx] = Wo[(size_t)(k0 + i) * H_ + n0 + tx];
        __syncthreads();
        for (int i = ty; i < 32; i += 8)
            g_woh[(size_t)(n0 + i) * H_ + k0 + tx] = __float2half(t[tx][i]);
        return;
    }
}

// ---------------- fp16 tensor-core GEMM ----------------
#define ASTR 40
#define STAGE_HALVES (3 * 128 * ASTR)

__global__ __launch_bounds__(256) void gemm_bf(
    const __half* __restrict__ Ahg, const __half* __restrict__ Alg,
    const __half* __restrict__ Bg,
    const float* __restrict__ bias, float* __restrict__ C,
    int M, int N, int K, int act)
{
    extern __shared__ __half smh[];
    int tid = threadIdx.x;
    int row0 = blockIdx.y * 128, col0 = blockIdx.x * 128;
    int wid = tid >> 5, lane = tid & 31;
    int wm = (wid >> 1) * 32, wn = (wid & 1) * 64;
    int g = lane >> 2, t = lane & 3;
    int lr = lane & 7, seg = lane >> 3;
    bool two = (Alg != nullptr);

    float acc[2][8][4];
#pragma unroll
    for (int i = 0; i < 2; i++)
#pragma unroll
        for (int j = 0; j < 8; j++)
#pragma unroll
            for (int q = 0; q < 4; q++) acc[i][j][q] = 0.f;

    const __half* gsrc[3] = {Ahg, Alg, Bg};
    int gr0[3] = {row0, row0, col0};

    auto load_stage = [&](int s, int k0) {
        __half* sp = smh + s * STAGE_HALVES;
#pragma unroll
        for (int a = 0; a < 3; a++) {
            if (a == 1 && !two) continue;
#pragma unroll
            for (int q = 0; q < 2; q++) {
                int c = tid * 2 + q;
                int r = c >> 2, sg = c & 3;
                uint32_t d = SMEMU32(sp + a * 128 * ASTR + r * ASTR + sg * 8);
                cpa16(d, gsrc[a] + (size_t)(gr0[a] + r) * K + k0 + sg * 8);
            }
        }
        CPA_COMMIT;
    };

    load_stage(0, 0);
    int nk = K / 32;
    for (int ki = 0; ki < nk; ki++) {
        if (ki + 1 < nk) {
            load_stage((ki + 1) & 1, (ki + 1) * 32);
            asm volatile("cp.async.wait_group 1;");
        } else {
            asm volatile("cp.async.wait_group 0;");
        }
        __syncthreads();
        __half* sp = smh + (ki & 1) * STAGE_HALVES;
        __half* Ah = sp;
        __half* Al = sp + 128 * ASTR;
        __half* Bs = sp + 2 * 128 * ASTR;
#pragma unroll
        for (int ks = 0; ks < 2; ks++) {
            int ko = ks * 16;
            int arow = wm + lr + ((seg & 1) << 3);
            int acol = ko + ((seg >> 1) << 3);
            uint32_t afh[2][4], afl[2][4];
#pragma unroll
            for (int mi = 0; mi < 2; mi++) {
                LDSM4(afh[mi][0], afh[mi][1], afh[mi][2], afh[mi][3],
                      SMEMU32(&Ah[(arow + mi * 16) * ASTR + acol]));
                if (two)
                    LDSM4(afl[mi][0], afl[mi][1], afl[mi][2], afl[mi][3],
                          SMEMU32(&Al[(arow + mi * 16) * ASTR + acol]));
            }
            int brow = wn + lr + ((seg >> 1) << 3);
            int bcol = ko + ((seg & 1) << 3);
            uint32_t b4[4][4];
#pragma unroll
            for (int nip = 0; nip < 4; nip++)
                LDSM4(b4[nip][0], b4[nip][1], b4[nip][2], b4[nip][3],
                      SMEMU32(&Bs[(brow + nip * 16) * ASTR + bcol]));
#pragma unroll
            for (int ni = 0; ni < 8; ni++) {
                uint32_t b0 = b4[ni >> 1][(ni & 1) * 2];
                uint32_t b1 = b4[ni >> 1][(ni & 1) * 2 + 1];
                MMAH16816(acc[0][ni], afh[0], b0, b1);
                MMAH16816(acc[1][ni], afh[1], b0, b1);
            }
            if (two) {
#pragma unroll
                for (int ni = 0; ni < 8; ni++) {
                    uint32_t b0 = b4[ni >> 1][(ni & 1) * 2];
                    uint32_t b1 = b4[ni >> 1][(ni & 1) * 2 + 1];
                    MMAH16816(acc[0][ni], afl[0], b0, b1);
                    MMAH16816(acc[1][ni], afl[1], b0, b1);
                }
            }
        }
        __syncthreads();
    }

#pragma unroll
    for (int mi = 0; mi < 2; mi++)
#pragma unroll
        for (int ni = 0; ni < 8; ni++) {
            int r = row0 + wm + mi * 16 + g;
            int c = col0 + wn + ni * 8 + 2 * t;
            float v[4];
#pragma unroll
            for (int q = 0; q < 4; q++) {
                float x = acc[mi][ni][q];
                if (bias) x += bias[c + (q & 1)];
                if (act == 1) x = 0.5f * x * (1.f + erff(x * 0.70710678118654752f));
                v[q] = x;
            }
            *(float2*)(C + (size_t)r * N + c)       = make_float2(v[0], v[1]);
            *(float2*)(C + (size_t)(r + 8) * N + c) = make_float2(v[2], v[3]);
        }
}

// ---------------- fused causal conv K=4 + silu (q,k,v one launch) ----------------
__global__ void conv3_kernel(const float* __restrict__ cq,
                             const float* __restrict__ ck,
                             const float* __restrict__ cv)
{
    int z = blockIdx.y;
    const float* w = (z == 0) ? cq : (z == 1) ? ck : cv;
    float* dst = (z == 0) ? g_q : (z == 1) ? g_k : g_v;
    int srcOff = z * H_;

    int tid = blockIdx.x * blockDim.x + threadIdx.x;
    int c = tid & (H_ - 1);
    int r = tid >> 10;
    int b = r >> 11;
    int l = r & (L_ - 1);
    const float* wc = w + c * 4;
    float acc = 0.f;
#pragma unroll
    for (int j = 0; j < 4; j++) {
        int ll = l - 3 + j;
        if (ll >= 0) acc += g_qkv[(size_t)(b * L_ + ll) * 3 * H_ + srcOff + c] * wc[j];
    }
    dst[tid] = acc / (1.f + expf(-acc));
}

// ---------------- delta precompute ----------------
#define RS 260
__global__ __launch_bounds__(256) void precomp_kernel()
{
    extern __shared__ float sm[];
    float* Qs = sm;
    float* Ks = Qs + 32 * RS;
    float* KB = Ks + 32 * RS;
    float* VB = KB + 32 * RS;
    float* Am = VB + 32 * RS;
    float* Tm = Am + 1024;
    __shared__ float rbeta[32], qn_s[32], kn_s[32];

    int bhn = blockIdx.x;
    int n = bhn % NCH_; int bh = bhn / NCH_;
    int b = bh >> 2, h = bh & 3;
    int l0 = n * 32;
    int tid = threadIdx.x, wi = tid >> 5, lane = tid & 31;

    for (int e = tid; e < 8192; e += 256) {
        int i = e >> 8, d = e & 255;
        size_t gi = ((size_t)(b * L_ + l0 + i) << 10) + h * 256 + d;
        Qs[i * RS + d] = g_q[gi];
        Ks[i * RS + d] = g_k[gi];
    }
    if (tid < 32) rbeta[tid] = g_beta[(b * L_ + l0 + tid) * 4 + h];
    __syncthreads();

    for (int rr = wi; rr < 32; rr += 8) {
        float sq = 0, sk = 0;
        for (int d = lane; d < 256; d += 32) {
            float a = Qs[rr * RS + d]; sq += a * a;
            float c = Ks[rr * RS + d]; sk += c * c;
        }
#pragma unroll
        for (int off = 16; off; off >>= 1) {
            sq += __shfl_down_sync(~0u, sq, off);
            sk += __shfl_down_sync(~0u, sk, off);
        }
        if (lane == 0) { qn_s[rr] = rsqrtf(sq + 1e-6f); kn_s[rr] = rsqrtf(sk + 1e-6f); }
    }
    __syncthreads();

    for (int e = tid; e < 8192; e += 256) {
        int i = e >> 8, d = e & 255;
        size_t gi = ((size_t)(b * L_ + l0 + i) << 10) + h * 256 + d;
        float qv = Qs[i * RS + d] * qn_s[i]; Qs[i * RS + d] = qv;
        float kv = Ks[i * RS + d] * kn_s[i]; Ks[i * RS + d] = kv;
        KB[i * RS + d] = kv * rbeta[i];
        VB[i * RS + d] = g_v[gi] * rbeta[i];
        g_tq[gi] = __float2half(qv);
    }
    __syncthreads();

    {
        size_t ckb = ((size_t)bh * NCH_ + n) * 8192;
        for (int e4 = tid; e4 < 2048; e4 += 256) {
            int i = e4 & 31, d0 = (e4 >> 5) * 4;
            float4 kv = *(const float4*)(Ks + i * RS + d0);
            g_tkt[ckb + (size_t)(d0 + 0) * 32 + i] = __float2half(kv.x);
            g_tkt[ckb + (size_t)(d0 + 1) * 32 + i] = __float2half(kv.y);
            g_tkt[ckb + (size_t)(d0 + 2) * 32 + i] = __float2half(kv.z);
            g_tkt[ckb + (size_t)(d0 + 3) * 32 + i] = __float2half(kv.w);
        }
    }

    for (int e = tid; e < 1024; e += 256) {
        int i = e >> 5, j = e & 31;
        float s = 0.f;
        if (j < i) {
            const float4* a = (const float4*)(KB + i * RS);
            const float4* c = (const float4*)(Ks + j * RS);
#pragma unroll 8
            for (int d = 0; d < 64; d++) {
                float4 av = a[d], cv = c[d];
                s += av.x * cv.x + av.y * cv.y + av.z * cv.z + av.w * cv.w;
            }
        }
        Am[e] = s;
    }
    __syncthreads();

    if (wi == 0) {
        int j = lane;
        for (int i = 0; i < 32; i++) {
            float val = (i == j) ? 1.f : 0.f;
            for (int m = j; m < i; m++) val -= Am[i * 32 + m] * Tm[m * 32 + j];
            Tm[i * 32 + j] = val;
            __syncwarp();
        }
    }
    __syncthreads();

    {
        size_t ab = ((size_t)bh * NCH_ + n) * 1024;
        for (int e = tid; e < 1024; e += 256) {
            int i = e >> 5, j = e & 31;
            float s = 0.f;
            if (j <= i) {
                const float4* a = (const float4*)(Qs + i * RS);
                const float4* c = (const float4*)(Ks + j * RS);
#pragma unroll 8
                for (int d = 0; d < 64; d++) {
                    float4 av = a[d], cv = c[d];
                    s += av.x * cv.x + av.y * cv.y + av.z * cv.z + av.w * cv.w;
                }
            }
            g_ta[ab + e] = __float2half(s);
        }
    }

    for (int e4 = tid; e4 < 2048; e4 += 256) {
        int i = e4 >> 6, d0 = (e4 & 63) * 4;
        float4 su = make_float4(0.f, 0.f, 0.f, 0.f);
        float4 sw = make_float4(0.f, 0.f, 0.f, 0.f);
        const float* tr = Tm + i * 32;
#pragma unroll
        for (int m = 0; m < 32; m++) {
            float t = tr[m];
            float4 vb = *(const float4*)(VB + m * RS + d0);
            float4 kb = *(const float4*)(KB + m * RS + d0);
            su.x += t * vb.x; su.y += t * vb.y; su.z += t * vb.z; su.w += t * vb.w;
            sw.x += t * kb.x; sw.y += t * kb.y; sw.z += t * kb.z; sw.w += t * kb.w;
        }
        size_t gi = ((size_t)(b * L_ + l0 + i) << 10) + h * 256 + d0;
        *(float4*)(g_qp + gi) = su;
        __half2* wp = (__half2*)(g_tw + gi);
        wp[0] = __floats2half2_rn(sw.x, sw.y);
        wp[1] = __floats2half2_rn(sw.z, sw.w);
    }
}

// ---------------- tensor-core scan (round-13 validated: single KT, late issue) ----
#define SC_SMEM 135168
#define STG_OFF 58368
#define STG_SZ  38400

__global__ __launch_bounds__(256) void scan_kernel()
{
    extern __shared__ char sc[];
    float* S  = (float*)sc;
    float* U2 = (float*)(sc + 16384);
    __half* SbTh = (__half*)(sc + 18432);
    __half* SbTl = (__half*)(sc + 26880);
    __half* U2Th = (__half*)(sc + 35328);
    __half* U2Tl = (__half*)(sc + 36608);
    __half* KT   = (__half*)(sc + 37888);

    int blk = blockIdx.x;
    int bh = blk >> 4, slice = blk & 15;
    int b = bh >> 2, h = bh & 3;
    int tid = threadIdx.x;
    int wi = tid >> 5, lane = tid & 31;
    int g = lane >> 2, t4 = lane & 3;
    int dvb = h * 256 + slice * 16;

    for (int e = tid; e < 4096; e += 256) S[e] = 0.f;
    for (int e = tid; e < 16 * 264; e += 256) {
        SbTh[e] = __float2half(0.f);
        SbTl[e] = __float2half(0.f);
    }

    auto issue_main = [&](int n, int buf) {
        char* sp = sc + STG_OFF + buf * STG_SZ;
        __half* Wt = (__half*)sp;
        __half* Qt = (__half*)(sp + 16896);
        float*  Uf = (float*)(sp + 33792);
        __half* At = (__half*)(sp + 35840);
        int row0 = b * L_ + n * 32;
#pragma unroll
        for (int it = 0; it < 8; it++) {
            int c = tid + it * 256;
            int a = c >> 10, rem = c & 1023;
            int r = rem >> 5, s = rem & 31;
            __half* dst = a ? Qt : Wt;
            const __half* src = a ? g_tq : g_tw;
            cpa16(SMEMU32(dst + r * 264 + s * 8),
                  src + ((size_t)(row0 + r) << 10) + h * 256 + s * 8);
        }
        if (tid < 128) {
            int r = tid >> 2, s = tid & 3;
            cpa16(SMEMU32(Uf + r * 16 + s * 4),
                  g_qp + ((size_t)(row0 + r) << 10) + dvb + s * 4);
        }
        if (tid < 128) {
            int r = tid >> 2, s = tid & 3;
            cpa16(SMEMU32(At + r * 40 + s * 8),
                  g_ta + ((size_t)bh * NCH_ + n) * 1024 + r * 32 + s * 8);
        }
        CPA_COMMIT;
    };

    auto issue_kT = [&](int n) {
        size_t base = ((size_t)bh * NCH_ + n) * 8192;
#pragma unroll
        for (int it = 0; it < 4; it++) {
            int c = tid + it * 256;
            int r = c >> 2, s = c & 3;
            cpa16(SMEMU32(KT + r * 40 + s * 8), g_tkt + base + r * 32 + s * 8);
        }
        CPA_COMMIT;
    };

    issue_main(0, 0);
    issue_kT(0);
    int buf = 0;

#pragma unroll 1
    for (int n = 0; n < NCH_; n++) {
        asm volatile("cp.async.wait_group 0;");
        if (n + 1 < NCH_) issue_main(n + 1, buf ^ 1);
        __syncthreads();

        char* sp = sc + STG_OFF + buf * STG_SZ;
        const __half* Wt = (const __half*)sp;
        const __half* Qt = (const __half*)(sp + 16896);
        const float*  Uf = (const float*)(sp + 33792);
        const __half* At = (const __half*)(sp + 35840);

        float c0[4] = {0,0,0,0}, c1[4] = {0,0,0,0};
        int w4 = wi & 3;
        int m0 = (w4 >> 1) * 16, n0 = (w4 & 1) * 8;
        const __half* Am_ = (wi < 4) ? Wt : Qt;
#pragma unroll
        for (int kk = 0; kk < 16; kk++) {
            int ka = kk * 16 + 2 * t4;
            uint32_t ah[4];
            ah[0] = *(const uint32_t*)&Am_[(m0 + g) * 264 + ka];
            ah[1] = *(const uint32_t*)&Am_[(m0 + 8 + g) * 264 + ka];
            ah[2] = *(const uint32_t*)&Am_[(m0 + g) * 264 + ka + 8];
            ah[3] = *(const uint32_t*)&Am_[(m0 + 8 + g) * 264 + ka + 8];
            uint32_t bh0 = *(const uint32_t*)&SbTh[(n0 + g) * 264 + ka];
            uint32_t bh1 = *(const uint32_t*)&SbTh[(n0 + g) * 264 + ka + 8];
            uint32_t bl0 = *(const uint32_t*)&SbTl[(n0 + g) * 264 + ka];
            uint32_t bl1 = *(const uint32_t*)&SbTl[(n0 + g) * 264 + ka + 8];
            MMAH16816(c0, ah, bh0, bh1);
            MMAH16816(c1, ah, bl0, bl1);
        }
        if (wi < 4) {
            U2[(m0 + g) * 16 + n0 + 2 * t4]         = Uf[(m0 + g) * 16 + n0 + 2 * t4]         - (c0[0] + c1[0]);
            U2[(m0 + g) * 16 + n0 + 2 * t4 + 1]     = Uf[(m0 + g) * 16 + n0 + 2 * t4 + 1]     - (c0[1] + c1[1]);
            U2[(m0 + 8 + g) * 16 + n0 + 2 * t4]     = Uf[(m0 + 8 + g) * 16 + n0 + 2 * t4]     - (c0[2] + c1[2]);
            U2[(m0 + 8 + g) * 16 + n0 + 2 * t4 + 1] = Uf[(m0 + 8 + g) * 16 + n0 + 2 * t4 + 1] - (c0[3] + c1[3]);
        }
        __syncthreads();

#pragma unroll
        for (int q2 = 0; q2 < 2; q2++) {
            int e = tid + q2 * 256;
            int i2 = e >> 4, j2 = e & 15;
            float v = U2[i2 * 16 + j2];
            __half hv = __float2half(v);
            U2Th[j2 * 40 + i2] = hv;
            U2Tl[j2 * 40 + i2] = __float2half(v - __half2float(hv));
        }
        __syncthreads();

        if (wi >= 4) {
#pragma unroll
            for (int kk = 0; kk < 2; kk++) {
                int ka = kk * 16 + 2 * t4;
                uint32_t ah[4];
                ah[0] = *(const uint32_t*)&At[(m0 + g) * 40 + ka];
                ah[1] = *(const uint32_t*)&At[(m0 + 8 + g) * 40 + ka];
                ah[2] = *(const uint32_t*)&At[(m0 + g) * 40 + ka + 8];
                ah[3] = *(const uint32_t*)&At[(m0 + 8 + g) * 40 + ka + 8];
                uint32_t bh0 = *(const uint32_t*)&U2Th[(n0 + g) * 40 + ka];
                uint32_t bh1 = *(const uint32_t*)&U2Th[(n0 + g) * 40 + ka + 8];
                uint32_t bl0 = *(const uint32_t*)&U2Tl[(n0 + g) * 40 + ka];
                uint32_t bl1 = *(const uint32_t*)&U2Tl[(n0 + g) * 40 + ka + 8];
                MMAH16816(c0, ah, bh0, bh1);
                MMAH16816(c1, ah, bl0, bl1);
            }
            size_t ob = ((size_t)(b * L_ + n * 32) << 10) + dvb + n0 + 2 * t4;
            *(float2*)(g_vp + ob + ((size_t)(m0 + g) << 10)) =
                make_float2(c0[0] + c1[0], c0[1] + c1[1]);
            *(float2*)(g_vp + ob + ((size_t)(m0 + 8 + g) << 10)) =
                make_float2(c0[2] + c1[2], c0[3] + c1[3]);
        }

#pragma unroll
        for (int mm = 0; mm < 2; mm++)
#pragma unroll
        for (int nn = 0; nn < 2; nn++) {
            int m0p = (wi * 2 + mm) * 16, n0p = nn * 8;
            float d0[4];
            float2 s01 = *(float2*)(S + (m0p + g) * 16 + n0p + 2 * t4);
            float2 s23 = *(float2*)(S + (m0p + 8 + g) * 16 + n0p + 2 * t4);
            d0[0] = s01.x; d0[1] = s01.y; d0[2] = s23.x; d0[3] = s23.y;
#pragma unroll
            for (int kk = 0; kk < 2; kk++) {
                int ka = kk * 16 + 2 * t4;
                uint32_t ah[4];
                ah[0] = *(const uint32_t*)&KT[(m0p + g) * 40 + ka];
                ah[1] = *(const uint32_t*)&KT[(m0p + 8 + g) * 40 + ka];
                ah[2] = *(const uint32_t*)&KT[(m0p + g) * 40 + ka + 8];
                ah[3] = *(const uint32_t*)&KT[(m0p + 8 + g) * 40 + ka + 8];
                uint32_t bh0 = *(const uint32_t*)&U2Th[(n0p + g) * 40 + ka];
                uint32_t bh1 = *(const uint32_t*)&U2Th[(n0p + g) * 40 + ka + 8];
                uint32_t bl0 = *(const uint32_t*)&U2Tl[(n0p + g) * 40 + ka];
                uint32_t bl1 = *(const uint32_t*)&U2Tl[(n0p + g) * 40 + ka + 8];
                MMAH16816(d0, ah, bh0, bh1);
                MMAH16816(d0, ah, bl0, bl1);
            }
            *(float2*)(S + (m0p + g) * 16 + n0p + 2 * t4)     = make_float2(d0[0], d0[1]);
            *(float2*)(S + (m0p + 8 + g) * 16 + n0p + 2 * t4) = make_float2(d0[2], d0[3]);
        }
        __syncthreads();

        if (n + 1 < NCH_) issue_kT(n + 1);

        {
            int j = tid & 15, kb = tid >> 4;
#pragma unroll
            for (int m = 0; m < 16; m++) {
                int k = kb + m * 16;
                float v = S[k * 16 + j];
                __half hv = __float2half(v);
                SbTh[j * 264 + k] = hv;
                SbTl[j * 264 + k] = __float2half(v - __half2float(hv));
            }
        }
        __syncthreads();
        buf ^= 1;
    }
}

// ---------------- FIR convs ----------------
__global__ __launch_bounds__(256) void fir_kernel(const float* __restrict__ ws,
                                                  const float* __restrict__ wl)
{
    __shared__ float vt[94][64];
    __shared__ float wls[64 * 63];
    __shared__ float wss[64 * 3];
    int cb = blockIdx.x;
    int lb = blockIdx.y;
    int b = lb >> 6;
    int l0 = (lb & 63) * 32;
    int c0 = cb * 64;
    int tid = threadIdx.x;

    for (int e = tid; e < 94 * 64; e += 256) {
        int rr = e >> 6, cc = e & 63;
        int l = l0 - 62 + rr;
        vt[rr][cc] = (l >= 0) ? g_v[((size_t)(b * L_ + l) << 10) + c0 + cc] : 0.f;
    }
    for (int e = tid; e < 64 * 63; e += 256) wls[e] = wl[(size_t)c0 * 63 + e];
    for (int e = tid; e < 64 * 3; e += 256)  wss[e] = ws[(size_t)c0 * 3 + e];
    __syncthreads();

    for (int e = tid; e < 32 * 64; e += 256) {
        int i = e >> 6, cc = e & 63;
        float aL = 0.f, aS = 0.f;
        const float* wlr = wls + cc * 63;
#pragma unroll 9
        for (int j = 0; j < 63; j++) aL += vt[i + j][cc] * wlr[j];
        const float* wsr = wss + cc * 3;
#pragma unroll
        for (int j = 0; j < 3; j++) aS += vt[i + 60 + j][cc] * wsr[j];
        size_t gi = ((size_t)(b * L_ + l0 + i) << 10) + c0 + cc;
        g_fl[gi] = aL;
        g_fs[gi] = aS;
    }
}

// ---------------- gate input: write fp16 directly ----------------
__global__ void gate_kernel(const float* __restrict__ x)
{
    __shared__ float stats[32];
    int r = blockIdx.x, tid = threadIdx.x;
    int wi = tid >> 5, lane = tid & 31;
    for (int p = wi; p < 16; p += 8) {
        int br = p >> 2, h = p & 3;
        const float* src = (br == 0 ? g_fs : br == 1 ? g_fl : br == 2 ? g_vp : g_v)
                           + ((size_t)r << 10) + h * 256;
        float s = 0, s2 = 0;
        for (int d = lane; d < 256; d += 32) { float t = src[d]; s += t; s2 += t * t; }
#pragma unroll
        for (int off = 16; off; off >>= 1) {
            s += __shfl_down_sync(~0u, s, off);
            s2 += __shfl_down_sync(~0u, s2, off);
        }
        if (lane == 0) {
            float mean = s * (1.f / 256.f);
            float var = s2 * (1.f / 256.f) - mean * mean;
            stats[br * 8 + h] = mean;
            stats[br * 8 + 4 + h] = sqrtf(fmaxf(var, 1e-6f));
        }
    }
    __syncthreads();
    const float* xr = x + (size_t)r * H_;
    size_t gb = (size_t)r * GIN_;
    for (int e = tid; e < GIN_; e += 256) {
        float v = (e < H_) ? xr[e] : stats[e - H_];
        g_gh[gb + e] = __float2half(v);
    }
}

// ---------------- fused MLP2 + softmax gate + combine + RMSNorm ----------------
__global__ __launch_bounds__(256) void mc_kernel(const float* __restrict__ w2,
                                                 const float* __restrict__ b2,
                                                 const float* __restrict__ ltemp,
                                                 const float* __restrict__ onw)
{
    int r = blockIdx.x, tid = threadIdx.x;
    int wi = tid >> 5, lane = tid & 31;
    __shared__ float part[8][16];
    __shared__ float lg[16];
    __shared__ float wsum[8];
    __shared__ float bcast;

    // MLP2: logits = h @ w2 + b2
    float acc[16];
#pragma unroll
    for (int o = 0; o < 16; o++) acc[o] = 0.f;
    const float* hr = g_mlp + (size_t)r * MLPH_;
    for (int kk = tid; kk < MLPH_; kk += 256) {
        float hv = hr[kk];
        const float4* wr = (const float4*)(w2 + (size_t)kk * 16);
        float4 w0 = wr[0], w1 = wr[1], w2v = wr[2], w3 = wr[3];
        acc[0] += hv * w0.x; acc[1] += hv * w0.y; acc[2] += hv * w0.z; acc[3] += hv * w0.w;
        acc[4] += hv * w1.x; acc[5] += hv * w1.y; acc[6] += hv * w1.z; acc[7] += hv * w1.w;
        acc[8] += hv * w2v.x; acc[9] += hv * w2v.y; acc[10] += hv * w2v.z; acc[11] += hv * w2v.w;
        acc[12] += hv * w3.x; acc[13] += hv * w3.y; acc[14] += hv * w3.z; acc[15] += hv * w3.w;
    }
#pragma unroll
    for (int o = 0; o < 16; o++) {
        float v = acc[o];
#pragma unroll
        for (int off = 16; off; off >>= 1) v += __shfl_down_sync(~0u, v, off);
        if (lane == 0) part[wi][o] = v;
    }
    __syncthreads();
    if (tid < 16) {
        float s = b2[tid];
#pragma unroll
        for (int q = 0; q < 8; q++) s += part[q][tid];
        lg[tid] = s;
    }
    __syncthreads();

    // combine + RMSNorm
#pragma unroll 1
    for (int h = 0; h < 4; h++) {
        float temp = log1pf(expf(ltemp[h])) + 1e-4f;
        float l0 = lg[h * 4 + 0] / temp, l1 = lg[h * 4 + 1] / temp;
        float l2 = lg[h * 4 + 2] / temp, l3 = lg[h * 4 + 3] / temp;
        float mx = fmaxf(fmaxf(l0, l1), fmaxf(l2, l3));
        float e0 = expf(l0 - mx), e1 = expf(l1 - mx), e2 = expf(l2 - mx), e3 = expf(l3 - mx);
        float inv = 1.f / (e0 + e1 + e2 + e3);
        size_t idx = ((size_t)r << 10) + h * 256 + tid;
        float ov = (e0 * g_fs[idx] + e1 * g_fl[idx] + e2 * g_vp[idx] + e3 * g_v[idx]) * inv;
        float sq = ov * ov;
#pragma unroll
        for (int off = 16; off; off >>= 1) sq += __shfl_down_sync(~0u, sq, off);
        if (lane == 0) wsum[wi] = sq;
        __syncthreads();
        if (tid == 0) {
            float s = 0.f;
#pragma unroll
            for (int q = 0; q < 8; q++) s += wsum[q];
            bcast = rsqrtf(s * (1.f / 256.f) + 1e-5f);
        }
        __syncthreads();
        float val = ov * bcast * onw[tid];
        g_xh[idx] = __float2half(val);
        __syncthreads();
    }
}

// ---------------- launch ----------------
extern "C" void kernel_launch(void* const* d_in, const int* in_sizes, int n_in,
                              void* d_out, int out_size)
{
    const float* x   = (const float*)d_in[0];
    const float* Wq  = (const float*)d_in[1];
    const float* Wk  = (const float*)d_in[2];
    const float* Wv  = (const float*)d_in[3];
    const float* Wb  = (const float*)d_in[4];
    const float* cq  = (const float*)d_in[5];
    const float* ck  = (const float*)d_in[6];
    const float* cv  = (const float*)d_in[7];
    const float* fsw = (const float*)d_in[8];
    const float* flw = (const float*)d_in[9];
    const float* w1  = (const float*)d_in[10];
    const float* b1  = (const float*)d_in[11];
    const float* w2  = (const float*)d_in[12];
    const float* b2  = (const float*)d_in[13];
    const float* lt  = (const float*)d_in[14];
    const float* onw = (const float*)d_in[15];
    const float* Wo  = (const float*)d_in[16];
    float* out = (float*)d_out;

    void* p;
    float *qkv, *mlp;
    __half *wh, *w1h, *woh, *xh, *gh;
    cudaGetSymbolAddress(&p, g_qkv); qkv = (float*)p;
    cudaGetSymbolAddress(&p, g_mlp); mlp = (float*)p;
    cudaGetSymbolAddress(&p, g_wh);  wh = (__half*)p;
    cudaGetSymbolAddress(&p, g_w1h); w1h = (__half*)p;
    cudaGetSymbolAddress(&p, g_woh); woh = (__half*)p;
    cudaGetSymbolAddress(&p, g_xh);  xh = (__half*)p;
    cudaGetSymbolAddress(&p, g_gh);  gh = (__half*)p;

    static int attr_done = 0;
    if (!attr_done) {
        cudaFuncSetAttribute(gemm_bf, cudaFuncAttributeMaxDynamicSharedMemorySize,
                             2 * STAGE_HALVES * (int)sizeof(__half));
        cudaFuncSetAttribute(precomp_kernel, cudaFuncAttributeMaxDynamicSharedMemorySize,
                             (4 * 32 * RS + 2048) * (int)sizeof(float));
        cudaFuncSetAttribute(scan_kernel, cudaFuncAttributeMaxDynamicSharedMemorySize,
                             SC_SMEM);
        attr_done = 1;
    }

    dim3 thr(256);
    int gsm = 2 * STAGE_HALVES * (int)sizeof(__half);

    // 1) merged prep: split + QKV-weight conv + beta + w1 conv + Wo conv
    prep_kernel<<<NB_PREP, thr>>>(x, Wq, Wk, Wv, Wb, w1, Wo);
    // 2) QKV gemm (single-pass fp16)
    gemm_bf<<<dim3(3 * H_ / 128, R_ / 128), thr, gsm>>>(xh, nullptr, wh, nullptr, qkv,
                                                        R_, 3 * H_, H_, 0);
    // 3) short convs + silu
    conv3_kernel<<<dim3(R_ * H_ / 256, 3), thr>>>(cq, ck, cv);
    // 4) delta precompute
    precomp_kernel<<<B_ * NH_ * NCH_, thr,
                     (4 * 32 * RS + 2048) * sizeof(float)>>>();
    // 5) sequential scan
    scan_kernel<<<128, 256, SC_SMEM>>>();
    // 6) FIR convs
    fir_kernel<<<dim3(H_ / 64, B_ * L_ / 32), thr>>>(fsw, flw);
    // 7) gate input
    gate_kernel<<<R_, thr>>>(x);
    // 8) MLP1 (single-pass fp16, gelu+bias fused)
    gemm_bf<<<dim3(MLPH_ / 128, R_ / 128), thr, gsm>>>(gh, nullptr, w1h, b1, mlp,
                                                       R_, MLPH_, GIN_, 1);
    // 9) fused MLP2 + combine + RMSNorm
    mc_kernel<<<R_, thr>>>(w2, b2, lt, onw);
    // 10) output projection (single-pass fp16)
    gemm_bf<<<dim3(H_ / 128, R_ / 128), thr, gsm>>>(xh, nullptr, woh, nullptr, out,
                                                    R_, H_, H_, 0);
}

// round 17
// speedup vs baseline: 1.1093x; 1.0571x over previous
#include <cuda_runtime.h>
#include <cuda_bf16.h>
#include <cuda_fp16.h>
#include <stdint.h>
#include <math.h>

#define B_   2
#define L_   2048
#define H_   1024
#define NH_  4
#define R_   (B_ * L_)       // 4096 rows
#define NCH_ 64              // chunks of 32 per sequence
#define GIN_ 1056
#define MLPH_ 2048

// ---------------- scratch ----------------
__device__ __align__(128) float g_qkv[(size_t)R_ * 3 * H_];
__device__ __align__(128) float g_qp[R_ * H_];     // u (fp32)
__device__ __align__(128) float g_vp[R_ * H_];     // delta_out
__device__ __align__(128) float g_q[R_ * H_];      // conv+silu q
__device__ __align__(128) float g_k[R_ * H_];      // conv+silu k
__device__ __align__(128) float g_v[R_ * H_];      // conv+silu v
__device__ __align__(128) float g_beta[R_ * NH_];
__device__ __align__(128) float g_fs[R_ * H_];
__device__ __align__(128) float g_fl[R_ * H_];
__device__ __align__(128) float g_mlp[(size_t)R_ * MLPH_];

// fp16 tiles for the scan (emitted by precomp; A-side single precision)
__device__ __align__(128) __half g_tq[R_ * H_];
__device__ __align__(128) __half g_tw[R_ * H_];
__device__ __align__(128) __half g_tkt[(size_t)B_*NH_*NCH_*8192];   // kT [bh][n][256][32]
__device__ __align__(128) __half g_ta[(size_t)B_*NH_*NCH_*1024];    // attn [bh][n][32][32]

// fp16 weights [N][K] (QKV packed: 3072 x 1024)
__device__ __align__(128) __half g_wh[3 * H_ * H_];
__device__ __align__(128) __half g_w1h[MLPH_ * GIN_];
__device__ __align__(128) __half g_woh[H_ * H_];
// fp16 activations
__device__ __align__(128) __half g_xh[R_ * H_];   // x, later oc
__device__ __align__(128) __half g_gh[(size_t)R_ * GIN_];

// ---------------- asm helpers ----------------
__device__ __forceinline__ void cpa16(uint32_t dst, const void* src) {
    asm volatile("cp.async.cg.shared.global [%0], [%1], 16;" :: "r"(dst), "l"(src));
}
#define CPA_COMMIT asm volatile("cp.async.commit_group;")
#define SMEMU32(p) ((uint32_t)__cvta_generic_to_shared(p))

#define MMAH16816(d, a, b0, b1) \
  asm volatile("mma.sync.aligned.m16n8k16.row.col.f32.f16.f16.f32 " \
    "{%0,%1,%2,%3}, {%4,%5,%6,%7}, {%8,%9}, {%0,%1,%2,%3};" \
    : "+f"(d[0]), "+f"(d[1]), "+f"(d[2]), "+f"(d[3]) \
    : "r"(a[0]), "r"(a[1]), "r"(a[2]), "r"(a[3]), "r"(b0), "r"(b1))

#define LDSM4(r0, r1, r2, r3, addr) \
  asm volatile("ldmatrix.sync.aligned.m8n8.x4.shared.b16 {%0,%1,%2,%3}, [%4];" \
    : "=r"(r0), "=r"(r1), "=r"(r2), "=r"(r3) : "r"(addr))

// ---------------- merged prep: split + wconv3 + beta + wconv(w1) + wconv(Wo) -----
#define NB_SPLIT (R_ * H_ / 256)           // 16384
#define NB_WC3   3072
#define NB_BETA  (R_ / 8)                  // 512
#define NB_W1    (64 * 33)                 // 2112
#define NB_WO    1024
#define NB_PREP  (NB_SPLIT + NB_WC3 + NB_BETA + NB_W1 + NB_WO)

__global__ __launch_bounds__(256) void prep_kernel(
    const float* __restrict__ x,
    const float* __restrict__ Wq, const float* __restrict__ Wk,
    const float* __restrict__ Wv, const float* __restrict__ Wb,
    const float* __restrict__ w1, const float* __restrict__ Wo)
{
    __shared__ float t[32][33];
    int bid = blockIdx.x;
    int tid = threadIdx.x;

    if (bid < NB_SPLIT) {
        int i = bid * 256 + tid;
        g_xh[i] = __float2half(x[i]);
        return;
    }
    bid -= NB_SPLIT;
    if (bid < NB_WC3) {
        int z = bid >> 10, rem = bid & 1023;
        int k0 = (rem >> 5) * 32, n0 = (rem & 31) * 32;
        const float* W = (z == 0) ? Wq : (z == 1) ? Wk : Wv;
        int tx = tid & 31, ty = tid >> 5;
        for (int i = ty; i < 32; i += 8)
            t[i][tx] = W[(size_t)(k0 + i) * H_ + n0 + tx];
        __syncthreads();
        size_t base = (size_t)z * H_ * H_;
        for (int i = ty; i < 32; i += 8)
            g_wh[base + (size_t)(n0 + i) * H_ + k0 + tx] = __float2half(t[tx][i]);
        return;
    }
    bid -= NB_WC3;
    if (bid < NB_BETA) {
        int r = bid * 8 + (tid >> 5);
        int lane = tid & 31;
        float acc0 = 0, acc1 = 0, acc2 = 0, acc3 = 0;
        const float* xr = x + (size_t)r * H_;
        for (int kk = lane * 4; kk < H_; kk += 128) {
            float4 xv = *(const float4*)(xr + kk);
#pragma unroll
            for (int e = 0; e < 4; e++) {
                float xs = (e == 0) ? xv.x : (e == 1) ? xv.y : (e == 2) ? xv.z : xv.w;
                float4 w = *(const float4*)(Wb + (kk + e) * 4);
                acc0 += xs * w.x; acc1 += xs * w.y; acc2 += xs * w.z; acc3 += xs * w.w;
            }
        }
#pragma unroll
        for (int off = 16; off; off >>= 1) {
            acc0 += __shfl_down_sync(~0u, acc0, off);
            acc1 += __shfl_down_sync(~0u, acc1, off);
            acc2 += __shfl_down_sync(~0u, acc2, off);
            acc3 += __shfl_down_sync(~0u, acc3, off);
        }
        if (lane == 0) {
            g_beta[r * 4 + 0] = 1.f / (1.f + expf(-acc0));
            g_beta[r * 4 + 1] = 1.f / (1.f + expf(-acc1));
            g_beta[r * 4 + 2] = 1.f / (1.f + expf(-acc2));
            g_beta[r * 4 + 3] = 1.f / (1.f + expf(-acc3));
        }
        return;
    }
    bid -= NB_BETA;
    if (bid < NB_W1) {
        int n0 = (bid & 63) * 32, k0 = (bid >> 6) * 32;
        int tx = tid & 31, ty = tid >> 5;
        for (int i = ty; i < 32; i += 8)
            t[i][tx] = w1[(size_t)(k0 + i) * MLPH_ + n0 + tx];
        __syncthreads();
        for (int i = ty; i < 32; i += 8)
            g_w1h[(size_t)(n0 + i) * GIN_ + k0 + tx] = __float2half(t[tx][i]);
        return;
    }
    bid -= NB_W1;
    {
        int n0 = (bid & 31) * 32, k0 = (bid >> 5) * 32;
        int tx = tid & 31, ty = tid >> 5;
        for (int i = ty; i < 32; i += 8)
            t[i][tx] = Wo[(size_t)(k0 + i) * H_ + n0 + tx];
        __syncthreads();
        for (int i = ty; i < 32; i += 8)
            g_woh[(size_t)(n0 + i) * H_ + k0 + tx] = __float2half(t[tx][i]);
        return;
    }
}

// ---------------- fp16 tensor-core GEMM ----------------
#define ASTR 40
#define STAGE_HALVES (3 * 128 * ASTR)

__global__ __launch_bounds__(256) void gemm_bf(
    const __half* __restrict__ Ahg, const __half* __restrict__ Alg,
    const __half* __restrict__ Bg,
    const float* __restrict__ bias, float* __restrict__ C,
    int M, int N, int K, int act)
{
    extern __shared__ __half smh[];
    int tid = threadIdx.x;
    int row0 = blockIdx.y * 128, col0 = blockIdx.x * 128;
    int wid = tid >> 5, lane = tid & 31;
    int wm = (wid >> 1) * 32, wn = (wid & 1) * 64;
    int g = lane >> 2, t = lane & 3;
    int lr = lane & 7, seg = lane >> 3;
    bool two = (Alg != nullptr);

    float acc[2][8][4];
#pragma unroll
    for (int i = 0; i < 2; i++)
#pragma unroll
        for (int j = 0; j < 8; j++)
#pragma unroll
            for (int q = 0; q < 4; q++) acc[i][j][q] = 0.f;

    const __half* gsrc[3] = {Ahg, Alg, Bg};
    int gr0[3] = {row0, row0, col0};

    auto load_stage = [&](int s, int k0) {
        __half* sp = smh + s * STAGE_HALVES;
#pragma unroll
        for (int a = 0; a < 3; a++) {
            if (a == 1 && !two) continue;
#pragma unroll
            for (int q = 0; q < 2; q++) {
                int c = tid * 2 + q;
                int r = c >> 2, sg = c & 3;
                uint32_t d = SMEMU32(sp + a * 128 * ASTR + r * ASTR + sg * 8);
                cpa16(d, gsrc[a] + (size_t)(gr0[a] + r) * K + k0 + sg * 8);
            }
        }
        CPA_COMMIT;
    };

    load_stage(0, 0);
    int nk = K / 32;
    for (int ki = 0; ki < nk; ki++) {
        if (ki + 1 < nk) {
            load_stage((ki + 1) & 1, (ki + 1) * 32);
            asm volatile("cp.async.wait_group 1;");
        } else {
            asm volatile("cp.async.wait_group 0;");
        }
        __syncthreads();
        __half* sp = smh + (ki & 1) * STAGE_HALVES;
        __half* Ah = sp;
        __half* Al = sp + 128 * ASTR;
        __half* Bs = sp + 2 * 128 * ASTR;
#pragma unroll
        for (int ks = 0; ks < 2; ks++) {
            int ko = ks * 16;
            int arow = wm + lr + ((seg & 1) << 3);
            int acol = ko + ((seg >> 1) << 3);
            uint32_t afh[2][4], afl[2][4];
#pragma unroll
            for (int mi = 0; mi < 2; mi++) {
                LDSM4(afh[mi][0], afh[mi][1], afh[mi][2], afh[mi][3],
                      SMEMU32(&Ah[(arow + mi * 16) * ASTR + acol]));
                if (two)
                    LDSM4(afl[mi][0], afl[mi][1], afl[mi][2], afl[mi][3],
                          SMEMU32(&Al[(arow + mi * 16) * ASTR + acol]));
            }
            int brow = wn + lr + ((seg >> 1) << 3);
            int bcol = ko + ((seg & 1) << 3);
            uint32_t b4[4][4];
#pragma unroll
            for (int nip = 0; nip < 4; nip++)
                LDSM4(b4[nip][0], b4[nip][1], b4[nip][2], b4[nip][3],
                      SMEMU32(&Bs[(brow + nip * 16) * ASTR + bcol]));
#pragma unroll
            for (int ni = 0; ni < 8; ni++) {
                uint32_t b0 = b4[ni >> 1][(ni & 1) * 2];
                uint32_t b1 = b4[ni >> 1][(ni & 1) * 2 + 1];
                MMAH16816(acc[0][ni], afh[0], b0, b1);
                MMAH16816(acc[1][ni], afh[1], b0, b1);
            }
            if (two) {
#pragma unroll
                for (int ni = 0; ni < 8; ni++) {
                    uint32_t b0 = b4[ni >> 1][(ni & 1) * 2];
                    uint32_t b1 = b4[ni >> 1][(ni & 1) * 2 + 1];
                    MMAH16816(acc[0][ni], afl[0], b0, b1);
                    MMAH16816(acc[1][ni], afl[1], b0, b1);
                }
            }
        }
        __syncthreads();
    }

#pragma unroll
    for (int mi = 0; mi < 2; mi++)
#pragma unroll
        for (int ni = 0; ni < 8; ni++) {
            int r = row0 + wm + mi * 16 + g;
            int c = col0 + wn + ni * 8 + 2 * t;
            float v[4];
#pragma unroll
            for (int q = 0; q < 4; q++) {
                float x = acc[mi][ni][q];
                if (bias) x += bias[c + (q & 1)];
                if (act == 1) x = 0.5f * x * (1.f + erff(x * 0.70710678118654752f));
                v[q] = x;
            }
            *(float2*)(C + (size_t)r * N + c)       = make_float2(v[0], v[1]);
            *(float2*)(C + (size_t)(r + 8) * N + c) = make_float2(v[2], v[3]);
        }
}

// ---------------- fused causal conv K=4 + silu (q,k,v one launch) ----------------
__global__ void conv3_kernel(const float* __restrict__ cq,
                             const float* __restrict__ ck,
                             const float* __restrict__ cv)
{
    int z = blockIdx.y;
    const float* w = (z == 0) ? cq : (z == 1) ? ck : cv;
    float* dst = (z == 0) ? g_q : (z == 1) ? g_k : g_v;
    int srcOff = z * H_;

    int tid = blockIdx.x * blockDim.x + threadIdx.x;
    int c = tid & (H_ - 1);
    int r = tid >> 10;
    int b = r >> 11;
    int l = r & (L_ - 1);
    const float* wc = w + c * 4;
    float acc = 0.f;
#pragma unroll
    for (int j = 0; j < 4; j++) {
        int ll = l - 3 + j;
        if (ll >= 0) acc += g_qkv[(size_t)(b * L_ + ll) * 3 * H_ + srcOff + c] * wc[j];
    }
    dst[tid] = acc / (1.f + expf(-acc));
}

// ---------------- delta precompute: beta folded into T; smem 108KB; 2 blocks/SM --
#define RS 260
#define PRE_SMEM ((3 * 32 * RS + 2048) * sizeof(float))
__global__ __launch_bounds__(256, 2) void precomp_kernel()
{
    extern __shared__ float sm[];
    float* Qs = sm;
    float* Ks = Qs + 32 * RS;
    float* Vs = Ks + 32 * RS;
    float* Am = Vs + 32 * RS;
    float* Tm = Am + 1024;
    __shared__ float rbeta[32], qn_s[32], kn_s[32];

    int bhn = blockIdx.x;
    int n = bhn % NCH_; int bh = bhn / NCH_;
    int b = bh >> 2, h = bh & 3;
    int l0 = n * 32;
    int tid = threadIdx.x, wi = tid >> 5, lane = tid & 31;

    for (int e = tid; e < 8192; e += 256) {
        int i = e >> 8, d = e & 255;
        size_t gi = ((size_t)(b * L_ + l0 + i) << 10) + h * 256 + d;
        Qs[i * RS + d] = g_q[gi];
        Ks[i * RS + d] = g_k[gi];
        Vs[i * RS + d] = g_v[gi];
    }
    if (tid < 32) rbeta[tid] = g_beta[(b * L_ + l0 + tid) * 4 + h];
    __syncthreads();

    for (int rr = wi; rr < 32; rr += 8) {
        float sq = 0, sk = 0;
        for (int d = lane; d < 256; d += 32) {
            float a = Qs[rr * RS + d]; sq += a * a;
            float c = Ks[rr * RS + d]; sk += c * c;
        }
#pragma unroll
        for (int off = 16; off; off >>= 1) {
            sq += __shfl_down_sync(~0u, sq, off);
            sk += __shfl_down_sync(~0u, sk, off);
        }
        if (lane == 0) { qn_s[rr] = rsqrtf(sq + 1e-6f); kn_s[rr] = rsqrtf(sk + 1e-6f); }
    }
    __syncthreads();

    for (int e = tid; e < 8192; e += 256) {
        int i = e >> 8, d = e & 255;
        size_t gi = ((size_t)(b * L_ + l0 + i) << 10) + h * 256 + d;
        float qv = Qs[i * RS + d] * qn_s[i]; Qs[i * RS + d] = qv;
        float kv = Ks[i * RS + d] * kn_s[i]; Ks[i * RS + d] = kv;
        g_tq[gi] = __float2half(qv);
    }
    __syncthreads();

    // kT tiles from normalized Ks
    {
        size_t ckb = ((size_t)bh * NCH_ + n) * 8192;
        for (int e4 = tid; e4 < 2048; e4 += 256) {
            int i = e4 & 31, d0 = (e4 >> 5) * 4;
            float4 kv = *(const float4*)(Ks + i * RS + d0);
            g_tkt[ckb + (size_t)(d0 + 0) * 32 + i] = __float2half(kv.x);
            g_tkt[ckb + (size_t)(d0 + 1) * 32 + i] = __float2half(kv.y);
            g_tkt[ckb + (size_t)(d0 + 2) * 32 + i] = __float2half(kv.z);
            g_tkt[ckb + (size_t)(d0 + 3) * 32 + i] = __float2half(kv.w);
        }
    }

    // A[i,j] = beta_i * (k_i . k_j), j < i
    for (int e = tid; e < 1024; e += 256) {
        int i = e >> 5, j = e & 31;
        float s = 0.f;
        if (j < i) {
            const float4* a = (const float4*)(Ks + i * RS);
            const float4* c = (const float4*)(Ks + j * RS);
#pragma unroll 4
            for (int d = 0; d < 64; d++) {
                float4 av = a[d], cv = c[d];
                s += av.x * cv.x + av.y * cv.y + av.z * cv.z + av.w * cv.w;
            }
            s *= rbeta[i];
        }
        Am[e] = s;
    }
    __syncthreads();

    if (wi == 0) {
        int j = lane;
        for (int i = 0; i < 32; i++) {
            float val = (i == j) ? 1.f : 0.f;
            for (int m = j; m < i; m++) val -= Am[i * 32 + m] * Tm[m * 32 + j];
            Tm[i * 32 + j] = val;
            __syncwarp();
        }
    }
    __syncthreads();

    // attn = tril(Qs @ Ks^T)
    {
        size_t ab = ((size_t)bh * NCH_ + n) * 1024;
        for (int e = tid; e < 1024; e += 256) {
            int i = e >> 5, j = e & 31;
            float s = 0.f;
            if (j <= i) {
                const float4* a = (const float4*)(Qs + i * RS);
                const float4* c = (const float4*)(Ks + j * RS);
#pragma unroll 4
                for (int d = 0; d < 64; d++) {
                    float4 av = a[d], cv = c[d];
                    s += av.x * cv.x + av.y * cv.y + av.z * cv.z + av.w * cv.w;
                }
            }
            g_ta[ab + e] = __float2half(s);
        }
    }

    // u_i = sum_m (T[i,m] beta_m) v_m ; w_i = sum_m (T[i,m] beta_m) k_m
    for (int e4 = tid; e4 < 2048; e4 += 256) {
        int i = e4 >> 6, d0 = (e4 & 63) * 4;
        float4 su = make_float4(0.f, 0.f, 0.f, 0.f);
        float4 sw = make_float4(0.f, 0.f, 0.f, 0.f);
        const float* tr = Tm + i * 32;
#pragma unroll 8
        for (int m = 0; m < 32; m++) {
            float t = tr[m] * rbeta[m];
            float4 vb = *(const float4*)(Vs + m * RS + d0);
            float4 kb = *(const float4*)(Ks + m * RS + d0);
            su.x += t * vb.x; su.y += t * vb.y; su.z += t * vb.z; su.w += t * vb.w;
            sw.x += t * kb.x; sw.y += t * kb.y; sw.z += t * kb.z; sw.w += t * kb.w;
        }
        size_t gi = ((size_t)(b * L_ + l0 + i) << 10) + h * 256 + d0;
        *(float4*)(g_qp + gi) = su;
        __half2* wp = (__half2*)(g_tw + gi);
        wp[0] = __floats2half2_rn(sw.x, sw.y);
        wp[1] = __floats2half2_rn(sw.z, sw.w);
    }
}

// ---------------- tensor-core scan (round-13 validated) ----------------
#define SC_SMEM 135168
#define STG_OFF 58368
#define STG_SZ  38400

__global__ __launch_bounds__(256) void scan_kernel()
{
    extern __shared__ char sc[];
    float* S  = (float*)sc;
    float* U2 = (float*)(sc + 16384);
    __half* SbTh = (__half*)(sc + 18432);
    __half* SbTl = (__half*)(sc + 26880);
    __half* U2Th = (__half*)(sc + 35328);
    __half* U2Tl = (__half*)(sc + 36608);
    __half* KT   = (__half*)(sc + 37888);

    int blk = blockIdx.x;
    int bh = blk >> 4, slice = blk & 15;
    int b = bh >> 2, h = bh & 3;
    int tid = threadIdx.x;
    int wi = tid >> 5, lane = tid & 31;
    int g = lane >> 2, t4 = lane & 3;
    int dvb = h * 256 + slice * 16;

    for (int e = tid; e < 4096; e += 256) S[e] = 0.f;
    for (int e = tid; e < 16 * 264; e += 256) {
        SbTh[e] = __float2half(0.f);
        SbTl[e] = __float2half(0.f);
    }

    auto issue_main = [&](int n, int buf) {
        char* sp = sc + STG_OFF + buf * STG_SZ;
        __half* Wt = (__half*)sp;
        __half* Qt = (__half*)(sp + 16896);
        float*  Uf = (float*)(sp + 33792);
        __half* At = (__half*)(sp + 35840);
        int row0 = b * L_ + n * 32;
#pragma unroll
        for (int it = 0; it < 8; it++) {
            int c = tid + it * 256;
            int a = c >> 10, rem = c & 1023;
            int r = rem >> 5, s = rem & 31;
            __half* dst = a ? Qt : Wt;
            const __half* src = a ? g_tq : g_tw;
            cpa16(SMEMU32(dst + r * 264 + s * 8),
                  src + ((size_t)(row0 + r) << 10) + h * 256 + s * 8);
        }
        if (tid < 128) {
            int r = tid >> 2, s = tid & 3;
            cpa16(SMEMU32(Uf + r * 16 + s * 4),
                  g_qp + ((size_t)(row0 + r) << 10) + dvb + s * 4);
        }
        if (tid < 128) {
            int r = tid >> 2, s = tid & 3;
            cpa16(SMEMU32(At + r * 40 + s * 8),
                  g_ta + ((size_t)bh * NCH_ + n) * 1024 + r * 32 + s * 8);
        }
        CPA_COMMIT;
    };

    auto issue_kT = [&](int n) {
        size_t base = ((size_t)bh * NCH_ + n) * 8192;
#pragma unroll
        for (int it = 0; it < 4; it++) {
            int c = tid + it * 256;
            int r = c >> 2, s = c & 3;
            cpa16(SMEMU32(KT + r * 40 + s * 8), g_tkt + base + r * 32 + s * 8);
        }
        CPA_COMMIT;
    };

    issue_main(0, 0);
    issue_kT(0);
    int buf = 0;

#pragma unroll 1
    for (int n = 0; n < NCH_; n++) {
        asm volatile("cp.async.wait_group 0;");
        if (n + 1 < NCH_) issue_main(n + 1, buf ^ 1);
        __syncthreads();

        char* sp = sc + STG_OFF + buf * STG_SZ;
        const __half* Wt = (const __half*)sp;
        const __half* Qt = (const __half*)(sp + 16896);
        const float*  Uf = (const float*)(sp + 33792);
        const __half* At = (const __half*)(sp + 35840);

        float c0[4] = {0,0,0,0}, c1[4] = {0,0,0,0};
        int w4 = wi & 3;
        int m0 = (w4 >> 1) * 16, n0 = (w4 & 1) * 8;
        const __half* Am_ = (wi < 4) ? Wt : Qt;
#pragma unroll
        for (int kk = 0; kk < 16; kk++) {
            int ka = kk * 16 + 2 * t4;
            uint32_t ah[4];
            ah[0] = *(const uint32_t*)&Am_[(m0 + g) * 264 + ka];
            ah[1] = *(const uint32_t*)&Am_[(m0 + 8 + g) * 264 + ka];
            ah[2] = *(const uint32_t*)&Am_[(m0 + g) * 264 + ka + 8];
            ah[3] = *(const uint32_t*)&Am_[(m0 + 8 + g) * 264 + ka + 8];
            uint32_t bh0 = *(const uint32_t*)&SbTh[(n0 + g) * 264 + ka];
            uint32_t bh1 = *(const uint32_t*)&SbTh[(n0 + g) * 264 + ka + 8];
            uint32_t bl0 = *(const uint32_t*)&SbTl[(n0 + g) * 264 + ka];
            uint32_t bl1 = *(const uint32_t*)&SbTl[(n0 + g) * 264 + ka + 8];
            MMAH16816(c0, ah, bh0, bh1);
            MMAH16816(c1, ah, bl0, bl1);
        }
        if (wi < 4) {
            U2[(m0 + g) * 16 + n0 + 2 * t4]         = Uf[(m0 + g) * 16 + n0 + 2 * t4]         - (c0[0] + c1[0]);
            U2[(m0 + g) * 16 + n0 + 2 * t4 + 1]     = Uf[(m0 + g) * 16 + n0 + 2 * t4 + 1]     - (c0[1] + c1[1]);
            U2[(m0 + 8 + g) * 16 + n0 + 2 * t4]     = Uf[(m0 + 8 + g) * 16 + n0 + 2 * t4]     - (c0[2] + c1[2]);
            U2[(m0 + 8 + g) * 16 + n0 + 2 * t4 + 1] = Uf[(m0 + 8 + g) * 16 + n0 + 2 * t4 + 1] - (c0[3] + c1[3]);
        }
        __syncthreads();

#pragma unroll
        for (int q2 = 0; q2 < 2; q2++) {
            int e = tid + q2 * 256;
            int i2 = e >> 4, j2 = e & 15;
            float v = U2[i2 * 16 + j2];
            __half hv = __float2half(v);
            U2Th[j2 * 40 + i2] = hv;
            U2Tl[j2 * 40 + i2] = __float2half(v - __half2float(hv));
        }
        __syncthreads();

        if (wi >= 4) {
#pragma unroll
            for (int kk = 0; kk < 2; kk++) {
                int ka = kk * 16 + 2 * t4;
                uint32_t ah[4];
                ah[0] = *(const uint32_t*)&At[(m0 + g) * 40 + ka];
                ah[1] = *(const uint32_t*)&At[(m0 + 8 + g) * 40 + ka];
                ah[2] = *(const uint32_t*)&At[(m0 + g) * 40 + ka + 8];
                ah[3] = *(const uint32_t*)&At[(m0 + 8 + g) * 40 + ka + 8];
                uint32_t bh0 = *(const uint32_t*)&U2Th[(n0 + g) * 40 + ka];
                uint32_t bh1 = *(const uint32_t*)&U2Th[(n0 + g) * 40 + ka + 8];
                uint32_t bl0 = *(const uint32_t*)&U2Tl[(n0 + g) * 40 + ka];
                uint32_t bl1 = *(const uint32_t*)&U2Tl[(n0 + g) * 40 + ka + 8];
                MMAH16816(c0, ah, bh0, bh1);
                MMAH16816(c1, ah, bl0, bl1);
            }
            size_t ob = ((size_t)(b * L_ + n * 32) << 10) + dvb + n0 + 2 * t4;
            *(float2*)(g_vp + ob + ((size_t)(m0 + g) << 10)) =
                make_float2(c0[0] + c1[0], c0[1] + c1[1]);
            *(float2*)(g_vp + ob + ((size_t)(m0 + 8 + g) << 10)) =
                make_float2(c0[2] + c1[2], c0[3] + c1[3]);
        }

#pragma unroll
        for (int mm = 0; mm < 2; mm++)
#pragma unroll
        for (int nn = 0; nn < 2; nn++) {
            int m0p = (wi * 2 + mm) * 16, n0p = nn * 8;
            float d0[4];
            float2 s01 = *(float2*)(S + (m0p + g) * 16 + n0p + 2 * t4);
            float2 s23 = *(float2*)(S + (m0p + 8 + g) * 16 + n0p + 2 * t4);
            d0[0] = s01.x; d0[1] = s01.y; d0[2] = s23.x; d0[3] = s23.y;
#pragma unroll
            for (int kk = 0; kk < 2; kk++) {
                int ka = kk * 16 + 2 * t4;
                uint32_t ah[4];
                ah[0] = *(const uint32_t*)&KT[(m0p + g) * 40 + ka];
                ah[1] = *(const uint32_t*)&KT[(m0p + 8 + g) * 40 + ka];
                ah[2] = *(const uint32_t*)&KT[(m0p + g) * 40 + ka + 8];
                ah[3] = *(const uint32_t*)&KT[(m0p + 8 + g) * 40 + ka + 8];
                uint32_t bh0 = *(const uint32_t*)&U2Th[(n0p + g) * 40 + ka];
                uint32_t bh1 = *(const uint32_t*)&U2Th[(n0p + g) * 40 + ka + 8];
                uint32_t bl0 = *(const uint32_t*)&U2Tl[(n0p + g) * 40 + ka];
                uint32_t bl1 = *(const uint32_t*)&U2Tl[(n0p + g) * 40 + ka + 8];
                MMAH16816(d0, ah, bh0, bh1);
                MMAH16816(d0, ah, bl0, bl1);
            }
            *(float2*)(S + (m0p + g) * 16 + n0p + 2 * t4)     = make_float2(d0[0], d0[1]);
            *(float2*)(S + (m0p + 8 + g) * 16 + n0p + 2 * t4) = make_float2(d0[2], d0[3]);
        }
        __syncthreads();

        if (n + 1 < NCH_) issue_kT(n + 1);

        {
            int j = tid & 15, kb = tid >> 4;
#pragma unroll
            for (int m = 0; m < 16; m++) {
                int k = kb + m * 16;
                float v = S[k * 16 + j];
                __half hv = __float2half(v);
                SbTh[j * 264 + k] = hv;
                SbTl[j * 264 + k] = __float2half(v - __half2float(hv));
            }
        }
        __syncthreads();
        buf ^= 1;
    }
}

// ---------------- FIR convs ----------------
__global__ __launch_bounds__(256) void fir_kernel(const float* __restrict__ ws,
                                                  const float* __restrict__ wl)
{
    __shared__ float vt[94][64];
    __shared__ float wls[64 * 63];
    __shared__ float wss[64 * 3];
    int cb = blockIdx.x;
    int lb = blockIdx.y;
    int b = lb >> 6;
    int l0 = (lb & 63) * 32;
    int c0 = cb * 64;
    int tid = threadIdx.x;

    for (int e = tid; e < 94 * 64; e += 256) {
        int rr = e >> 6, cc = e & 63;
        int l = l0 - 62 + rr;
        vt[rr][cc] = (l >= 0) ? g_v[((size_t)(b * L_ + l) << 10) + c0 + cc] : 0.f;
    }
    for (int e = tid; e < 64 * 63; e += 256) wls[e] = wl[(size_t)c0 * 63 + e];
    for (int e = tid; e < 64 * 3; e += 256)  wss[e] = ws[(size_t)c0 * 3 + e];
    __syncthreads();

    for (int e = tid; e < 32 * 64; e += 256) {
        int i = e >> 6, cc = e & 63;
        float aL = 0.f, aS = 0.f;
        const float* wlr = wls + cc * 63;
#pragma unroll 9
        for (int j = 0; j < 63; j++) aL += vt[i + j][cc] * wlr[j];
        const float* wsr = wss + cc * 3;
#pragma unroll
        for (int j = 0; j < 3; j++) aS += vt[i + 60 + j][cc] * wsr[j];
        size_t gi = ((size_t)(b * L_ + l0 + i) << 10) + c0 + cc;
        g_fl[gi] = aL;
        g_fs[gi] = aS;
    }
}

// ---------------- gate input: write fp16 directly ----------------
__global__ void gate_kernel(const float* __restrict__ x)
{
    __shared__ float stats[32];
    int r = blockIdx.x, tid = threadIdx.x;
    int wi = tid >> 5, lane = tid & 31;
    for (int p = wi; p < 16; p += 8) {
        int br = p >> 2, h = p & 3;
        const float* src = (br == 0 ? g_fs : br == 1 ? g_fl : br == 2 ? g_vp : g_v)
                           + ((size_t)r << 10) + h * 256;
        float s = 0, s2 = 0;
        for (int d = lane; d < 256; d += 32) { float t = src[d]; s += t; s2 += t * t; }
#pragma unroll
        for (int off = 16; off; off >>= 1) {
            s += __shfl_down_sync(~0u, s, off);
            s2 += __shfl_down_sync(~0u, s2, off);
        }
        if (lane == 0) {
            float mean = s * (1.f / 256.f);
            float var = s2 * (1.f / 256.f) - mean * mean;
            stats[br * 8 + h] = mean;
            stats[br * 8 + 4 + h] = sqrtf(fmaxf(var, 1e-6f));
        }
    }
    __syncthreads();
    const float* xr = x + (size_t)r * H_;
    size_t gb = (size_t)r * GIN_;
    for (int e = tid; e < GIN_; e += 256) {
        float v = (e < H_) ? xr[e] : stats[e - H_];
        g_gh[gb + e] = __float2half(v);
    }
}

// ---------------- fused MLP2 + softmax gate + combine + RMSNorm ----------------
__global__ __launch_bounds__(256) void mc_kernel(const float* __restrict__ w2,
                                                 const float* __restrict__ b2,
                                                 const float* __restrict__ ltemp,
                                                 const float* __restrict__ onw)
{
    int r = blockIdx.x, tid = threadIdx.x;
    int wi = tid >> 5, lane = tid & 31;
    __shared__ float part[8][16];
    __shared__ float lg[16];
    __shared__ float wsum[8];
    __shared__ float bcast;

    float acc[16];
#pragma unroll
    for (int o = 0; o < 16; o++) acc[o] = 0.f;
    const float* hr = g_mlp + (size_t)r * MLPH_;
    for (int kk = tid; kk < MLPH_; kk += 256) {
        float hv = hr[kk];
        const float4* wr = (const float4*)(w2 + (size_t)kk * 16);
        float4 w0 = wr[0], w1 = wr[1], w2v = wr[2], w3 = wr[3];
        acc[0] += hv * w0.x; acc[1] += hv * w0.y; acc[2] += hv * w0.z; acc[3] += hv * w0.w;
        acc[4] += hv * w1.x; acc[5] += hv * w1.y; acc[6] += hv * w1.z; acc[7] += hv * w1.w;
        acc[8] += hv * w2v.x; acc[9] += hv * w2v.y; acc[10] += hv * w2v.z; acc[11] += hv * w2v.w;
        acc[12] += hv * w3.x; acc[13] += hv * w3.y; acc[14] += hv * w3.z; acc[15] += hv * w3.w;
    }
#pragma unroll
    for (int o = 0; o < 16; o++) {
        float v = acc[o];
#pragma unroll
        for (int off = 16; off; off >>= 1) v += __shfl_down_sync(~0u, v, off);
        if (lane == 0) part[wi][o] = v;
    }
    __syncthreads();
    if (tid < 16) {
        float s = b2[tid];
#pragma unroll
        for (int q = 0; q < 8; q++) s += part[q][tid];
        lg[tid] = s;
    }
    __syncthreads();

#pragma unroll 1
    for (int h = 0; h < 4; h++) {
        float temp = log1pf(expf(ltemp[h])) + 1e-4f;
        float l0 = lg[h * 4 + 0] / temp, l1 = lg[h * 4 + 1] / temp;
        float l2 = lg[h * 4 + 2] / temp, l3 = lg[h * 4 + 3] / temp;
        float mx = fmaxf(fmaxf(l0, l1), fmaxf(l2, l3));
        float e0 = expf(l0 - mx), e1 = expf(l1 - mx), e2 = expf(l2 - mx), e3 = expf(l3 - mx);
        float inv = 1.f / (e0 + e1 + e2 + e3);
        size_t idx = ((size_t)r << 10) + h * 256 + tid;
        float ov = (e0 * g_fs[idx] + e1 * g_fl[idx] + e2 * g_vp[idx] + e3 * g_v[idx]) * inv;
        float sq = ov * ov;
#pragma unroll
        for (int off = 16; off; off >>= 1) sq += __shfl_down_sync(~0u, sq, off);
        if (lane == 0) wsum[wi] = sq;
        __syncthreads();
        if (tid == 0) {
            float s = 0.f;
#pragma unroll
            for (int q = 0; q < 8; q++) s += wsum[q];
            bcast = rsqrtf(s * (1.f / 256.f) + 1e-5f);
        }
        __syncthreads();
        float val = ov * bcast * onw[tid];
        g_xh[idx] = __float2half(val);
        __syncthreads();
    }
}

// ---------------- launch ----------------
extern "C" void kernel_launch(void* const* d_in, const int* in_sizes, int n_in,
                              void* d_out, int out_size)
{
    const float* x   = (const float*)d_in[0];
    const float* Wq  = (const float*)d_in[1];
    const float* Wk  = (const float*)d_in[2];
    const float* Wv  = (const float*)d_in[3];
    const float* Wb  = (const float*)d_in[4];
    const float* cq  = (const float*)d_in[5];
    const float* ck  = (const float*)d_in[6];
    const float* cv  = (const float*)d_in[7];
    const float* fsw = (const float*)d_in[8];
    const float* flw = (const float*)d_in[9];
    const float* w1  = (const float*)d_in[10];
    const float* b1  = (const float*)d_in[11];
    const float* w2  = (const float*)d_in[12];
    const float* b2  = (const float*)d_in[13];
    const float* lt  = (const float*)d_in[14];
    const float* onw = (const float*)d_in[15];
    const float* Wo  = (const float*)d_in[16];
    float* out = (float*)d_out;

    void* p;
    float *qkv, *mlp;
    __half *wh, *w1h, *woh, *xh, *gh;
    cudaGetSymbolAddress(&p, g_qkv); qkv = (float*)p;
    cudaGetSymbolAddress(&p, g_mlp); mlp = (float*)p;
    cudaGetSymbolAddress(&p, g_wh);  wh = (__half*)p;
    cudaGetSymbolAddress(&p, g_w1h); w1h = (__half*)p;
    cudaGetSymbolAddress(&p, g_woh); woh = (__half*)p;
    cudaGetSymbolAddress(&p, g_xh);  xh = (__half*)p;
    cudaGetSymbolAddress(&p, g_gh);  gh = (__half*)p;

    static int attr_done = 0;
    if (!attr_done) {
        cudaFuncSetAttribute(gemm_bf, cudaFuncAttributeMaxDynamicSharedMemorySize,
                             2 * STAGE_HALVES * (int)sizeof(__half));
        cudaFuncSetAttribute(precomp_kernel, cudaFuncAttributeMaxDynamicSharedMemorySize,
                             (int)PRE_SMEM);
        cudaFuncSetAttribute(scan_kernel, cudaFuncAttributeMaxDynamicSharedMemorySize,
                             SC_SMEM);
        attr_done = 1;
    }

    dim3 thr(256);
    int gsm = 2 * STAGE_HALVES * (int)sizeof(__half);

    // 1) merged prep
    prep_kernel<<<NB_PREP, thr>>>(x, Wq, Wk, Wv, Wb, w1, Wo);
    // 2) QKV gemm (single-pass fp16)
    gemm_bf<<<dim3(3 * H_ / 128, R_ / 128), thr, gsm>>>(xh, nullptr, wh, nullptr, qkv,
                                                        R_, 3 * H_, H_, 0);
    // 3) short convs + silu
    conv3_kernel<<<dim3(R_ * H_ / 256, 3), thr>>>(cq, ck, cv);
    // 4) delta precompute (108KB smem, 2 blocks/SM)
    precomp_kernel<<<B_ * NH_ * NCH_, thr, PRE_SMEM>>>();
    // 5) sequential scan
    scan_kernel<<<128, 256, SC_SMEM>>>();
    // 6) FIR convs
    fir_kernel<<<dim3(H_ / 64, B_ * L_ / 32), thr>>>(fsw, flw);
    // 7) gate input
    gate_kernel<<<R_, thr>>>(x);
    // 8) MLP1
    gemm_bf<<<dim3(MLPH_ / 128, R_ / 128), thr, gsm>>>(gh, nullptr, w1h, b1, mlp,
                                                       R_, MLPH_, GIN_, 1);
    // 9) fused MLP2 + combine + RMSNorm
    mc_kernel<<<R_, thr>>>(w2, b2, lt, onw);
    // 10) output projection
    gemm_bf<<<dim3(H_ / 128, R_ / 128), thr, gsm>>>(xh, nullptr, woh, nullptr, out,
                                                    R_, H_, H_, 0);
}